// round 1
// baseline (speedup 1.0000x reference)
#include <cuda_runtime.h>
#include <math.h>

#define Nn 512
#define Ee 16384
#define Dd 1280
#define LMd 1024
#define NFd 256
#define Mm 64

// ---- device scratch (no allocations allowed) ----
__device__ float g_h[Nn * Dd];      // concat features
__device__ float g_x[Nn * Dd];      // h + neigh (GEMM input)
__device__ float g_no[Nn * Dd];     // node_output
__device__ float g_p[Nn];           // projection
__device__ int   g_cnt[Nn];
__device__ int   g_off[Nn + 1];
__device__ int   g_cur[Nn];
__device__ int   g_es[Ee];          // edge ids sorted by dst

// ---------------------------------------------------------------
// K1: build h and zero counters
__global__ void k_build_h(const float* __restrict__ lm, const float* __restrict__ nf) {
    int idx = blockIdx.x * blockDim.x + threadIdx.x;
    if (idx < Nn) g_cnt[idx] = 0;
    if (idx >= Nn * Dd) return;
    int i = idx / Dd, j = idx - i * Dd;
    g_h[idx] = (j < LMd) ? lm[(i + 1) * LMd + j] : nf[i * NFd + (j - LMd)];
}

// K2: histogram of dst
__global__ void k_hist(const int* __restrict__ dst) {
    int e = blockIdx.x * blockDim.x + threadIdx.x;
    if (e < Ee) atomicAdd(&g_cnt[dst[e]], 1);
}

// K3: exclusive scan over 512 counters (one block, 512 threads)
__global__ void k_scan() {
    __shared__ int s[Nn];
    int t = threadIdx.x;
    s[t] = g_cnt[t];
    __syncthreads();
    for (int off = 1; off < Nn; off <<= 1) {
        int v = (t >= off) ? s[t - off] : 0;
        __syncthreads();
        s[t] += v;
        __syncthreads();
    }
    g_off[t + 1] = s[t];
    if (t == 0) g_off[0] = 0;
    g_cur[t] = s[t] - g_cnt[t];  // exclusive prefix
}

// K4: scatter edge ids into dst-sorted order
__global__ void k_scatter(const int* __restrict__ dst) {
    int e = blockIdx.x * blockDim.x + threadIdx.x;
    if (e < Ee) {
        int pos = atomicAdd(&g_cur[dst[e]], 1);
        g_es[pos] = e;
    }
}

// K5: per-dst max-aggregation; write g_x = h + neigh
__global__ void k_neigh(const int* __restrict__ src, const float* __restrict__ ew) {
    int d = blockIdx.x;
    int beg = g_off[d], end = g_off[d + 1];
    __shared__ int   ss[256];
    __shared__ float sw[256];
    float m[5];
#pragma unroll
    for (int t = 0; t < 5; t++) m[t] = -INFINITY;

    for (int c = beg; c < end; c += 256) {
        int nc = min(256, end - c);
        if (threadIdx.x < nc) {
            int e = g_es[c + threadIdx.x];
            ss[threadIdx.x] = src[e];
            sw[threadIdx.x] = ew[e];
        }
        __syncthreads();
        for (int j = 0; j < nc; j++) {
            const float* hr = g_h + ss[j] * Dd;
            float w = sw[j];
#pragma unroll
            for (int t = 0; t < 5; t++)
                m[t] = fmaxf(m[t], hr[threadIdx.x + t * 256] * w);
        }
        __syncthreads();
    }
#pragma unroll
    for (int t = 0; t < 5; t++) {
        int k = threadIdx.x + t * 256;
        float nv = (m[t] == -INFINITY) ? 0.f : m[t];
        g_x[d * Dd + k] = g_h[d * Dd + k] + nv;
    }
}

// K6: GEMM  g_no = g_x @ W_g + b_g + g_h   (512x1280 @ 1280x1280)
#define BM 64
#define BN 64
#define BK 16
__global__ __launch_bounds__(256, 2) void k_gemm(const float* __restrict__ Wg,
                                                 const float* __restrict__ bg) {
    __shared__ float As[BK][BM];   // A transposed: [k][m]
    __shared__ float Bs[BK][BN];
    int tid = threadIdx.x;
    int tx = tid & 15, ty = tid >> 4;
    int bm = blockIdx.y * BM;
    int bn = blockIdx.x * BN;

    float acc[4][4];
#pragma unroll
    for (int i = 0; i < 4; i++)
#pragma unroll
        for (int j = 0; j < 4; j++) acc[i][j] = 0.f;

    int arow = tid >> 2;            // 0..63
    int acol4 = (tid & 3) * 4;      // 0,4,8,12
    int brow = tid >> 4;            // 0..15
    int bcol4 = (tid & 15) * 4;     // 0..60

    const float* Xp = g_x + (bm + arow) * Dd + acol4;
    const float* Wp = Wg + brow * Dd + bn + bcol4;

    for (int k0 = 0; k0 < Dd; k0 += BK) {
        float4 a4 = *(const float4*)Xp;  Xp += BK;
        float4 b4 = *(const float4*)Wp;  Wp += BK * Dd;
        As[acol4 + 0][arow] = a4.x;
        As[acol4 + 1][arow] = a4.y;
        As[acol4 + 2][arow] = a4.z;
        As[acol4 + 3][arow] = a4.w;
        *(float4*)&Bs[brow][bcol4] = b4;
        __syncthreads();
#pragma unroll
        for (int kk = 0; kk < BK; kk++) {
            float4 av = *(const float4*)&As[kk][ty * 4];
            float4 bv = *(const float4*)&Bs[kk][tx * 4];
            acc[0][0] += av.x * bv.x; acc[0][1] += av.x * bv.y;
            acc[0][2] += av.x * bv.z; acc[0][3] += av.x * bv.w;
            acc[1][0] += av.y * bv.x; acc[1][1] += av.y * bv.y;
            acc[1][2] += av.y * bv.z; acc[1][3] += av.y * bv.w;
            acc[2][0] += av.z * bv.x; acc[2][1] += av.z * bv.y;
            acc[2][2] += av.z * bv.z; acc[2][3] += av.z * bv.w;
            acc[3][0] += av.w * bv.x; acc[3][1] += av.w * bv.y;
            acc[3][2] += av.w * bv.z; acc[3][3] += av.w * bv.w;
        }
        __syncthreads();
    }
#pragma unroll
    for (int i = 0; i < 4; i++) {
        int m = bm + ty * 4 + i;
#pragma unroll
        for (int j = 0; j < 4; j++) {
            int n = bn + tx * 4 + j;
            g_no[m * Dd + n] = acc[i][j] + bg[n] + g_h[m * Dd + n];
        }
    }
}

// K7: p = node_output @ W_d
__global__ void k_proj(const float* __restrict__ Wd) {
    int d = blockIdx.x;
    float s = 0.f;
    for (int k = threadIdx.x; k < Dd; k += 256)
        s += g_no[d * Dd + k] * Wd[k];
#pragma unroll
    for (int o = 16; o; o >>= 1) s += __shfl_down_sync(0xffffffff, s, o);
    __shared__ float red[8];
    int lane = threadIdx.x & 31, wid = threadIdx.x >> 5;
    if (lane == 0) red[wid] = s;
    __syncthreads();
    if (wid == 0) {
        s = (lane < 8) ? red[lane] : 0.f;
#pragma unroll
        for (int o = 4; o; o >>= 1) s += __shfl_down_sync(0xffffffff, s, o);
        if (lane == 0) g_p[d] = s;
    }
}

// K8: dis_pred[i][j] = sigmoid(p[j] - p[i] + b_d)
__global__ void k_dis(float* __restrict__ out, const float* __restrict__ bd) {
    int i = blockIdx.x;
    float pi = g_p[i];
    float b = bd[0];
    for (int j = threadIdx.x; j < Nn; j += blockDim.x) {
        float z = g_p[j] - pi + b;
        out[i * Nn + j] = 1.0f / (1.0f + expf(-z));
    }
}

// K9: mask_pred = tanh(node_output[mask_index] @ W_m + b_m)
__global__ void k_mask(const int* __restrict__ midx, const float* __restrict__ Wm,
                       const float* __restrict__ bm, float* __restrict__ out) {
    int b = blockIdx.x;
    int r = midx[b];
    float s0 = 0.f, s1 = 0.f;
    for (int k = threadIdx.x; k < Dd; k += 128) {
        float v = g_no[r * Dd + k];
        s0 += v * Wm[k * 2 + 0];
        s1 += v * Wm[k * 2 + 1];
    }
    __shared__ float red[2][4];
    int lane = threadIdx.x & 31, wid = threadIdx.x >> 5;
#pragma unroll
    for (int o = 16; o; o >>= 1) {
        s0 += __shfl_down_sync(0xffffffff, s0, o);
        s1 += __shfl_down_sync(0xffffffff, s1, o);
    }
    if (lane == 0) { red[0][wid] = s0; red[1][wid] = s1; }
    __syncthreads();
    if (threadIdx.x == 0) {
        s0 = red[0][0] + red[0][1] + red[0][2] + red[0][3];
        s1 = red[1][0] + red[1][1] + red[1][2] + red[1][3];
        out[Nn * Nn + b * 2 + 0] = tanhf(s0 + bm[0]);
        out[Nn * Nn + b * 2 + 1] = tanhf(s1 + bm[1]);
    }
}

extern "C" void kernel_launch(void* const* d_in, const int* in_sizes, int n_in,
                              void* d_out, int out_size) {
    const float* lm  = (const float*)d_in[0];
    const float* nf  = (const float*)d_in[1];
    const float* ew  = (const float*)d_in[2];
    const int*   src = (const int*)d_in[3];
    const int*   dst = (const int*)d_in[4];
    const int*   mi  = (const int*)d_in[5];
    const float* Wg  = (const float*)d_in[6];
    const float* bg  = (const float*)d_in[7];
    const float* Wd  = (const float*)d_in[8];
    const float* bd  = (const float*)d_in[9];
    const float* Wm  = (const float*)d_in[10];
    const float* bm  = (const float*)d_in[11];
    float* out = (float*)d_out;

    k_build_h<<<(Nn * Dd + 255) / 256, 256>>>(lm, nf);
    k_hist<<<(Ee + 255) / 256, 256>>>(dst);
    k_scan<<<1, Nn>>>();
    k_scatter<<<(Ee + 255) / 256, 256>>>(dst);
    k_neigh<<<Nn, 256>>>(src, ew);
    dim3 ggrid(Dd / BN, Nn / BM);
    k_gemm<<<ggrid, 256>>>(Wg, bg);
    k_proj<<<Nn, 256>>>(Wd);
    k_dis<<<Nn, 256>>>(out, bd);
    k_mask<<<Mm, 128>>>(mi, Wm, bm, out);
}

// round 4
// speedup vs baseline: 1.1991x; 1.1991x over previous
#include <cuda_runtime.h>
#include <cuda_bf16.h>
#include <stdint.h>
#include <math.h>

#define Nn 512
#define Ee 16384
#define Dd 1280
#define LMd 1024
#define NFd 256
#define Mm 64
#define KTOT 3840            // 3*Dd : [hi | hi | lo] x [hi | lo | hi]
#define KCc 32               // K per smem chunk
#define NCH (KTOT / KCc)     // 120

// ---- device scratch ----
__device__ float g_h[Nn * Dd];
__device__ float g_no[Nn * Dd];
__device__ float g_p[Nn];
__device__ int   g_off[Nn + 1];
__device__ int   g_es[Ee];
__device__ __nv_bfloat16 g_A[Nn * KTOT];     // X split, K-major
__device__ __nv_bfloat16 g_B[Dd * KTOT];     // W^T split, K-major

__device__ __forceinline__ uint32_t smem_u32(const void* p) {
    uint32_t a;
    asm("{ .reg .u64 t; cvta.to.shared.u64 t, %1; cvt.u32.u64 %0, t; }" : "=r"(a) : "l"(p));
    return a;
}

// =================== K1: build h ===================
__global__ void k_build_h(const float* __restrict__ lm, const float* __restrict__ nf) {
    int idx = blockIdx.x * blockDim.x + threadIdx.x;
    if (idx >= Nn * Dd) return;
    int i = idx / Dd, j = idx - i * Dd;
    g_h[idx] = (j < LMd) ? lm[(i + 1) * LMd + j] : nf[i * NFd + (j - LMd)];
}

// =================== K2: W transpose + bf16 hi/lo split ===================
__global__ void k_convW(const float* __restrict__ W) {
    __shared__ float tile[32][33];
    int n0 = blockIdx.x * 32, k0 = blockIdx.y * 32;
    int tx = threadIdx.x, ty = threadIdx.y;
#pragma unroll
    for (int i = 0; i < 4; i++)
        tile[ty + 8 * i][tx] = W[(k0 + ty + 8 * i) * Dd + n0 + tx];
    __syncthreads();
#pragma unroll
    for (int i = 0; i < 4; i++) {
        int n = n0 + ty + 8 * i, k = k0 + tx;
        float v = tile[tx][ty + 8 * i];
        __nv_bfloat16 hi = __float2bfloat16(v);
        __nv_bfloat16 lo = __float2bfloat16(v - __bfloat162float(hi));
        size_t b = (size_t)n * KTOT;
        g_B[b + k] = hi;            // pairs with A hi
        g_B[b + Dd + k] = lo;       // pairs with A hi
        g_B[b + 2 * Dd + k] = hi;   // pairs with A lo
    }
}

// =================== K3: CSR build (one block) ===================
__global__ void k_csr(const int* __restrict__ dst) {
    __shared__ int cnt[Nn];
    __shared__ int s[Nn];
    __shared__ int pos[Nn];
    int t = threadIdx.x;
    cnt[t] = 0;
    __syncthreads();
    for (int e = t; e < Ee; e += Nn) atomicAdd(&cnt[dst[e]], 1);
    __syncthreads();
    s[t] = cnt[t];
    __syncthreads();
    for (int off = 1; off < Nn; off <<= 1) {
        int v = (t >= off) ? s[t - off] : 0;
        __syncthreads();
        s[t] += v;
        __syncthreads();
    }
    g_off[t + 1] = s[t];
    if (t == 0) g_off[0] = 0;
    pos[t] = s[t] - cnt[t];
    __syncthreads();
    for (int e = t; e < Ee; e += Nn) {
        int d = dst[e];
        int p = atomicAdd(&pos[d], 1);
        g_es[p] = e;
    }
}

// =================== K4: neigh max + write split A ===================
__global__ void k_neigh(const int* __restrict__ src, const float* __restrict__ ew) {
    int d = blockIdx.x;
    int beg = g_off[d], end = g_off[d + 1];
    __shared__ int   ss[256];
    __shared__ float sw[256];
    float m[5];
#pragma unroll
    for (int t = 0; t < 5; t++) m[t] = -INFINITY;

    for (int c = beg; c < end; c += 256) {
        int nc = min(256, end - c);
        if (threadIdx.x < nc) {
            int e = g_es[c + threadIdx.x];
            ss[threadIdx.x] = src[e];
            sw[threadIdx.x] = ew[e];
        }
        __syncthreads();
        for (int j = 0; j < nc; j++) {
            const float* hr = g_h + ss[j] * Dd;
            float w = sw[j];
#pragma unroll
            for (int t = 0; t < 5; t++)
                m[t] = fmaxf(m[t], hr[threadIdx.x + t * 256] * w);
        }
        __syncthreads();
    }
    size_t ab = (size_t)d * KTOT;
#pragma unroll
    for (int t = 0; t < 5; t++) {
        int k = threadIdx.x + t * 256;
        float nv = (m[t] == -INFINITY) ? 0.f : m[t];
        float x = g_h[d * Dd + k] + nv;
        __nv_bfloat16 hi = __float2bfloat16(x);
        __nv_bfloat16 lo = __float2bfloat16(x - __bfloat162float(hi));
        g_A[ab + k] = hi;
        g_A[ab + Dd + k] = hi;
        g_A[ab + 2 * Dd + k] = lo;
    }
}

// =================== K5: mma.sync bf16 GEMM, 64x64 tiles ===================
// As/Bs: padded row stride 40 bf16 (80B) -> conflict-free b32 fragment loads.
#define SPAD 40
__global__ __launch_bounds__(128, 2) void k_gemm_mma(const float* __restrict__ bg) {
    __shared__ __nv_bfloat16 As[2][64 * SPAD];
    __shared__ __nv_bfloat16 Bs[2][64 * SPAD];
    int tid = threadIdx.x;
    int lane = tid & 31, warp = tid >> 5;
    int bm = blockIdx.y * 64, bn = blockIdx.x * 64;
    int wm = (warp >> 1) * 32, wn = (warp & 1) * 32;

    uint32_t sA[2], sB[2];
#pragma unroll
    for (int st = 0; st < 2; st++) {
        sA[st] = smem_u32(As[st]);
        sB[st] = smem_u32(Bs[st]);
    }

    float acc[2][4][4];
#pragma unroll
    for (int mf = 0; mf < 2; mf++)
#pragma unroll
        for (int nf = 0; nf < 4; nf++)
#pragma unroll
            for (int r = 0; r < 4; r++) acc[mf][nf][r] = 0.f;

    // per-thread load slots: 256 16B chunks per tile, 128 threads -> 2 each
    int r0 = tid >> 1;              // 0..63
    int s0 = (tid & 1) * 2;         // 0 or 2  (two consecutive segs handled below)

    // prologue: stage 0, chunk 0
#pragma unroll
    for (int q = 0; q < 2; q++) {
        int row = r0, seg = s0 + q;
        uint32_t da = sA[0] + row * (SPAD * 2) + seg * 16;
        uint32_t db = sB[0] + row * (SPAD * 2) + seg * 16;
        const void* pa = g_A + (size_t)(bm + row) * KTOT + seg * 8;
        const void* pb = g_B + (size_t)(bn + row) * KTOT + seg * 8;
        asm volatile("cp.async.cg.shared.global [%0], [%1], 16;" :: "r"(da), "l"(pa));
        asm volatile("cp.async.cg.shared.global [%0], [%1], 16;" :: "r"(db), "l"(pb));
    }
    asm volatile("cp.async.commit_group;" ::: "memory");

    for (int c = 0; c < NCH; c++) {
        int st = c & 1;
        if (c + 1 < NCH) {
            int k0 = (c + 1) * KCc;
#pragma unroll
            for (int q = 0; q < 2; q++) {
                int row = r0, seg = s0 + q;
                uint32_t da = sA[st ^ 1] + row * (SPAD * 2) + seg * 16;
                uint32_t db = sB[st ^ 1] + row * (SPAD * 2) + seg * 16;
                const void* pa = g_A + (size_t)(bm + row) * KTOT + k0 + seg * 8;
                const void* pb = g_B + (size_t)(bn + row) * KTOT + k0 + seg * 8;
                asm volatile("cp.async.cg.shared.global [%0], [%1], 16;" :: "r"(da), "l"(pa));
                asm volatile("cp.async.cg.shared.global [%0], [%1], 16;" :: "r"(db), "l"(pb));
            }
            asm volatile("cp.async.commit_group;" ::: "memory");
            asm volatile("cp.async.wait_group 1;" ::: "memory");
        } else {
            asm volatile("cp.async.wait_group 0;" ::: "memory");
        }
        __syncthreads();

        const uint32_t* A32 = (const uint32_t*)As[st];
        const uint32_t* B32 = (const uint32_t*)Bs[st];
#pragma unroll
        for (int ks = 0; ks < 2; ks++) {
            int ko = ks * 8;  // b32 offset within row
            uint32_t a[2][4];
#pragma unroll
            for (int mf = 0; mf < 2; mf++) {
                int base = (wm + mf * 16 + (lane >> 2)) * (SPAD / 2) + (lane & 3) + ko;
                a[mf][0] = A32[base];
                a[mf][1] = A32[base + 8 * (SPAD / 2)];
                a[mf][2] = A32[base + 4];
                a[mf][3] = A32[base + 8 * (SPAD / 2) + 4];
            }
            uint32_t b[4][2];
#pragma unroll
            for (int nf = 0; nf < 4; nf++) {
                int base = (wn + nf * 8 + (lane >> 2)) * (SPAD / 2) + (lane & 3) + ko;
                b[nf][0] = B32[base];
                b[nf][1] = B32[base + 4];
            }
#pragma unroll
            for (int mf = 0; mf < 2; mf++)
#pragma unroll
                for (int nf = 0; nf < 4; nf++) {
                    asm volatile(
                        "mma.sync.aligned.m16n8k16.row.col.f32.bf16.bf16.f32 "
                        "{%0,%1,%2,%3}, {%4,%5,%6,%7}, {%8,%9}, {%0,%1,%2,%3};"
                        : "+f"(acc[mf][nf][0]), "+f"(acc[mf][nf][1]),
                          "+f"(acc[mf][nf][2]), "+f"(acc[mf][nf][3])
                        : "r"(a[mf][0]), "r"(a[mf][1]), "r"(a[mf][2]), "r"(a[mf][3]),
                          "r"(b[nf][0]), "r"(b[nf][1]));
                }
        }
        __syncthreads();
    }

    // epilogue: D + bias + residual
#pragma unroll
    for (int mf = 0; mf < 2; mf++) {
        int row = bm + wm + mf * 16 + (lane >> 2);
#pragma unroll
        for (int nf = 0; nf < 4; nf++) {
            int col = bn + wn + nf * 8 + (lane & 3) * 2;
            g_no[row * Dd + col]           = acc[mf][nf][0] + bg[col]     + g_h[row * Dd + col];
            g_no[row * Dd + col + 1]       = acc[mf][nf][1] + bg[col + 1] + g_h[row * Dd + col + 1];
            g_no[(row + 8) * Dd + col]     = acc[mf][nf][2] + bg[col]     + g_h[(row + 8) * Dd + col];
            g_no[(row + 8) * Dd + col + 1] = acc[mf][nf][3] + bg[col + 1] + g_h[(row + 8) * Dd + col + 1];
        }
    }
}

// =================== K6: p = node_output @ W_d ===================
__global__ void k_proj(const float* __restrict__ Wd) {
    int d = blockIdx.x;
    float s = 0.f;
    for (int k = threadIdx.x; k < Dd; k += 256)
        s += g_no[d * Dd + k] * Wd[k];
#pragma unroll
    for (int o = 16; o; o >>= 1) s += __shfl_down_sync(0xffffffff, s, o);
    __shared__ float red[8];
    int lane = threadIdx.x & 31, wid = threadIdx.x >> 5;
    if (lane == 0) red[wid] = s;
    __syncthreads();
    if (wid == 0) {
        s = (lane < 8) ? red[lane] : 0.f;
#pragma unroll
        for (int o = 4; o; o >>= 1) s += __shfl_down_sync(0xffffffff, s, o);
        if (lane == 0) g_p[d] = s;
    }
}

// =================== K7: dis_pred ===================
__global__ void k_dis(float* __restrict__ out, const float* __restrict__ bd) {
    int i = blockIdx.x;
    float pi = g_p[i];
    float b = bd[0];
    for (int j = threadIdx.x; j < Nn; j += blockDim.x) {
        float z = g_p[j] - pi + b;
        out[i * Nn + j] = 1.0f / (1.0f + expf(-z));
    }
}

// =================== K8: mask_pred ===================
__global__ void k_mask(const int* __restrict__ midx, const float* __restrict__ Wm,
                       const float* __restrict__ bm, float* __restrict__ out) {
    int b = blockIdx.x;
    int r = midx[b];
    float s0 = 0.f, s1 = 0.f;
    for (int k = threadIdx.x; k < Dd; k += 128) {
        float v = g_no[r * Dd + k];
        s0 += v * Wm[k * 2 + 0];
        s1 += v * Wm[k * 2 + 1];
    }
    __shared__ float red[2][4];
    int lane = threadIdx.x & 31, wid = threadIdx.x >> 5;
#pragma unroll
    for (int o = 16; o; o >>= 1) {
        s0 += __shfl_down_sync(0xffffffff, s0, o);
        s1 += __shfl_down_sync(0xffffffff, s1, o);
    }
    if (lane == 0) { red[0][wid] = s0; red[1][wid] = s1; }
    __syncthreads();
    if (threadIdx.x == 0) {
        s0 = red[0][0] + red[0][1] + red[0][2] + red[0][3];
        s1 = red[1][0] + red[1][1] + red[1][2] + red[1][3];
        out[Nn * Nn + b * 2 + 0] = tanhf(s0 + bm[0]);
        out[Nn * Nn + b * 2 + 1] = tanhf(s1 + bm[1]);
    }
}

extern "C" void kernel_launch(void* const* d_in, const int* in_sizes, int n_in,
                              void* d_out, int out_size) {
    const float* lm  = (const float*)d_in[0];
    const float* nf  = (const float*)d_in[1];
    const float* ew  = (const float*)d_in[2];
    const int*   src = (const int*)d_in[3];
    const int*   dst = (const int*)d_in[4];
    const int*   mi  = (const int*)d_in[5];
    const float* Wg  = (const float*)d_in[6];
    const float* bg  = (const float*)d_in[7];
    const float* Wd  = (const float*)d_in[8];
    const float* bd  = (const float*)d_in[9];
    const float* Wm  = (const float*)d_in[10];
    const float* bm  = (const float*)d_in[11];
    float* out = (float*)d_out;

    k_build_h<<<(Nn * Dd + 255) / 256, 256>>>(lm, nf);
    k_convW<<<dim3(Dd / 32, Dd / 32), dim3(32, 8)>>>(Wg);
    k_csr<<<1, Nn>>>(dst);
    k_neigh<<<Nn, 256>>>(src, ew);
    k_gemm_mma<<<dim3(Dd / 64, Nn / 64), 128>>>(bg);
    k_proj<<<Nn, 256>>>(Wd);
    k_dis<<<Nn, 256>>>(out, bd);
    k_mask<<<Mm, 128>>>(mi, Wm, bm, out);
}

// round 5
// speedup vs baseline: 1.4978x; 1.2491x over previous
#include <cuda_runtime.h>
#include <cuda_bf16.h>
#include <stdint.h>
#include <math.h>

#define Nn 512
#define Ee 16384
#define Dd 1280
#define LMd 1024
#define NFd 256
#define Mm 64
#define KTOT 3840            // 3*Dd : [hi | hi | lo] x [hi | lo | hi]
#define KC2 64               // K per smem chunk
#define NC2 (KTOT / KC2)     // 60

// ---- device scratch ----
__device__ float g_h[Nn * Dd];
__device__ float g_no[Nn * Dd];
__device__ float g_p[Nn];
__device__ int   g_off[Nn + 1];
__device__ int   g_es[Ee];
__device__ __nv_bfloat16 g_A[Nn * KTOT];     // X split, K-major
__device__ __nv_bfloat16 g_B[Dd * KTOT];     // W^T split, K-major

__device__ __forceinline__ uint32_t smem_u32(const void* p) {
    uint32_t a;
    asm("{ .reg .u64 t; cvta.to.shared.u64 t, %1; cvt.u32.u64 %0, t; }" : "=r"(a) : "l"(p));
    return a;
}
__device__ __forceinline__ uint32_t pack_bf2(float a, float b) {
    __nv_bfloat162 t = __floats2bfloat162_rn(a, b);
    return *(uint32_t*)&t;
}

// =================== K1: build h (float4) ===================
__global__ void k_build_h(const float* __restrict__ lm, const float* __restrict__ nf) {
    int idx = blockIdx.x * blockDim.x + threadIdx.x;   // over Nn*320 float4s
    if (idx >= Nn * (Dd / 4)) return;
    int i = idx / (Dd / 4), j4 = idx - i * (Dd / 4);
    float4 v;
    if (j4 < LMd / 4) v = *(const float4*)(lm + (i + 1) * LMd + 4 * j4);
    else              v = *(const float4*)(nf + i * NFd + 4 * (j4 - LMd / 4));
    *(float4*)(g_h + i * Dd + 4 * j4) = v;
}

// =================== K2: W transpose + bf16 hi/lo split (paired stores) ===================
__global__ void k_convW(const float* __restrict__ W) {
    __shared__ float tile[32][33];
    int n0 = blockIdx.x * 32, k0 = blockIdx.y * 32;
    int tid = threadIdx.x;                 // 256
    int tx = tid & 31, ty = tid >> 5;      // load mapping 32x8
#pragma unroll
    for (int i = 0; i < 4; i++)
        tile[ty + 8 * i][tx] = W[(k0 + ty + 8 * i) * Dd + n0 + tx];
    __syncthreads();
    int p = tid & 15;          // k-pair 0..15
    int nr = tid >> 4;         // 0..15
#pragma unroll
    for (int i = 0; i < 2; i++) {
        int nn = nr + 16 * i;
        int n = n0 + nn;
        float v0 = tile[2 * p][nn], v1 = tile[2 * p + 1][nn];
        float h0f = __bfloat162float(__float2bfloat16(v0));
        float h1f = __bfloat162float(__float2bfloat16(v1));
        uint32_t hi2 = pack_bf2(v0, v1);
        uint32_t lo2 = pack_bf2(v0 - h0f, v1 - h1f);
        size_t b = (size_t)n * KTOT + k0 + 2 * p;
        *(uint32_t*)(g_B + b)          = hi2;   // pairs with A hi
        *(uint32_t*)(g_B + b + Dd)     = lo2;   // pairs with A hi
        *(uint32_t*)(g_B + b + 2 * Dd) = hi2;   // pairs with A lo
    }
}

// =================== K3: CSR build (one block) ===================
__global__ void k_csr(const int* __restrict__ dst) {
    __shared__ int cnt[Nn];
    __shared__ int s[Nn];
    __shared__ int pos[Nn];
    int t = threadIdx.x;
    cnt[t] = 0;
    __syncthreads();
    for (int e = t; e < Ee; e += Nn) atomicAdd(&cnt[dst[e]], 1);
    __syncthreads();
    s[t] = cnt[t];
    __syncthreads();
    for (int off = 1; off < Nn; off <<= 1) {
        int v = (t >= off) ? s[t - off] : 0;
        __syncthreads();
        s[t] += v;
        __syncthreads();
    }
    g_off[t + 1] = s[t];
    if (t == 0) g_off[0] = 0;
    pos[t] = s[t] - cnt[t];
    __syncthreads();
    for (int e = t; e < Ee; e += Nn) {
        int d = dst[e];
        int p = atomicAdd(&pos[d], 1);
        g_es[p] = e;
    }
}

// =================== K4: neigh max + write split A (float4, 320 thr) ===================
__global__ void k_neigh(const int* __restrict__ src, const float* __restrict__ ew) {
    int d = blockIdx.x;
    int beg = g_off[d], end = g_off[d + 1];
    int t = threadIdx.x;                    // 0..319
    __shared__ int   ss[128];
    __shared__ float sw[128];
    float4 m = make_float4(-INFINITY, -INFINITY, -INFINITY, -INFINITY);

    for (int c = beg; c < end; c += 128) {
        int nc = min(128, end - c);
        if (t < nc) {
            int e = g_es[c + t];
            ss[t] = src[e];
            sw[t] = ew[e];
        }
        __syncthreads();
        for (int j = 0; j < nc; j++) {
            const float4* hr = (const float4*)(g_h + ss[j] * Dd);
            float w = sw[j];
            float4 v = hr[t];
            m.x = fmaxf(m.x, v.x * w);
            m.y = fmaxf(m.y, v.y * w);
            m.z = fmaxf(m.z, v.z * w);
            m.w = fmaxf(m.w, v.w * w);
        }
        __syncthreads();
    }
    float4 hv = ((const float4*)(g_h + d * Dd))[t];
    float x0 = hv.x + ((m.x == -INFINITY) ? 0.f : m.x);
    float x1 = hv.y + ((m.y == -INFINITY) ? 0.f : m.y);
    float x2 = hv.z + ((m.z == -INFINITY) ? 0.f : m.z);
    float x3 = hv.w + ((m.w == -INFINITY) ? 0.f : m.w);
    float h0 = __bfloat162float(__float2bfloat16(x0));
    float h1 = __bfloat162float(__float2bfloat16(x1));
    float h2 = __bfloat162float(__float2bfloat16(x2));
    float h3 = __bfloat162float(__float2bfloat16(x3));
    uint32_t hiA = pack_bf2(x0, x1), hiB = pack_bf2(x2, x3);
    uint32_t loA = pack_bf2(x0 - h0, x1 - h1), loB = pack_bf2(x2 - h2, x3 - h3);
    size_t ab = (size_t)d * KTOT + 4 * t;
    *(uint32_t*)(g_A + ab) = hiA;              *(uint32_t*)(g_A + ab + 2) = hiB;
    *(uint32_t*)(g_A + ab + Dd) = hiA;         *(uint32_t*)(g_A + ab + Dd + 2) = hiB;
    *(uint32_t*)(g_A + ab + 2 * Dd) = loA;     *(uint32_t*)(g_A + ab + 2 * Dd + 2) = loB;
}

// =================== K5: mma.sync bf16 GEMM, 64x64 tiles, 3-stage, KC=64 ===================
#define SPAD2 72                 // bf16 row stride (144 B) -> conflict-free fragments
#define TILE_B (64 * SPAD2 * 2)  // 9216 B per operand tile
#define STAGE_B (2 * TILE_B)     // 18432 B per stage
__global__ __launch_bounds__(128, 2) void k_gemm_mma(const float* __restrict__ bg) {
    extern __shared__ __align__(16) unsigned char smem[];
    int tid = threadIdx.x;
    int lane = tid & 31, warp = tid >> 5;
    int bm = blockIdx.y * 64, bn = blockIdx.x * 64;
    int wm = (warp >> 1) * 32, wn = (warp & 1) * 32;

    uint32_t sbase = smem_u32(smem);
    uint32_t sA[3], sB[3];
#pragma unroll
    for (int st = 0; st < 3; st++) {
        sA[st] = sbase + st * STAGE_B;
        sB[st] = sA[st] + TILE_B;
    }

    float acc[2][4][4];
#pragma unroll
    for (int mf = 0; mf < 2; mf++)
#pragma unroll
        for (int nf = 0; nf < 4; nf++)
#pragma unroll
            for (int r = 0; r < 4; r++) acc[mf][nf][r] = 0.f;

    // load mapping: per operand tile 64 rows x 8 segs(16B) = 512 chunks, 4/thread
#define LOAD_CHUNK(cidx, st)                                                        \
    do {                                                                            \
        int k0 = (cidx) * KC2;                                                      \
        _Pragma("unroll")                                                           \
        for (int it = 0; it < 4; it++) {                                            \
            int idx = it * 128 + tid;                                               \
            int row = idx >> 3, seg = idx & 7;                                      \
            uint32_t da = sA[st] + row * (SPAD2 * 2) + seg * 16;                    \
            uint32_t db = sB[st] + row * (SPAD2 * 2) + seg * 16;                    \
            const void* pa = g_A + (size_t)(bm + row) * KTOT + k0 + seg * 8;        \
            const void* pb = g_B + (size_t)(bn + row) * KTOT + k0 + seg * 8;        \
            asm volatile("cp.async.cg.shared.global [%0], [%1], 16;" :: "r"(da), "l"(pa)); \
            asm volatile("cp.async.cg.shared.global [%0], [%1], 16;" :: "r"(db), "l"(pb)); \
        }                                                                           \
        asm volatile("cp.async.commit_group;" ::: "memory");                        \
    } while (0)

    LOAD_CHUNK(0, 0);
    LOAD_CHUNK(1, 1);

    for (int c = 0; c < NC2; c++) {
        int st = c % 3;
        if (c + 2 < NC2) {
            LOAD_CHUNK(c + 2, (c + 2) % 3);
            asm volatile("cp.async.wait_group 2;" ::: "memory");
        } else if (c + 1 < NC2) {
            asm volatile("cp.async.wait_group 1;" ::: "memory");
        } else {
            asm volatile("cp.async.wait_group 0;" ::: "memory");
        }
        __syncthreads();

        const uint32_t* A32 = (const uint32_t*)(smem + (size_t)st * STAGE_B);
        const uint32_t* B32 = (const uint32_t*)(smem + (size_t)st * STAGE_B + TILE_B);
#pragma unroll
        for (int ks = 0; ks < 4; ks++) {
            int ko = ks * 8;
            uint32_t a[2][4];
#pragma unroll
            for (int mf = 0; mf < 2; mf++) {
                int base = (wm + mf * 16 + (lane >> 2)) * (SPAD2 / 2) + (lane & 3) + ko;
                a[mf][0] = A32[base];
                a[mf][1] = A32[base + 8 * (SPAD2 / 2)];
                a[mf][2] = A32[base + 4];
                a[mf][3] = A32[base + 8 * (SPAD2 / 2) + 4];
            }
            uint32_t b[4][2];
#pragma unroll
            for (int nf = 0; nf < 4; nf++) {
                int base = (wn + nf * 8 + (lane >> 2)) * (SPAD2 / 2) + (lane & 3) + ko;
                b[nf][0] = B32[base];
                b[nf][1] = B32[base + 4];
            }
#pragma unroll
            for (int mf = 0; mf < 2; mf++)
#pragma unroll
                for (int nf = 0; nf < 4; nf++) {
                    asm volatile(
                        "mma.sync.aligned.m16n8k16.row.col.f32.bf16.bf16.f32 "
                        "{%0,%1,%2,%3}, {%4,%5,%6,%7}, {%8,%9}, {%0,%1,%2,%3};"
                        : "+f"(acc[mf][nf][0]), "+f"(acc[mf][nf][1]),
                          "+f"(acc[mf][nf][2]), "+f"(acc[mf][nf][3])
                        : "r"(a[mf][0]), "r"(a[mf][1]), "r"(a[mf][2]), "r"(a[mf][3]),
                          "r"(b[nf][0]), "r"(b[nf][1]));
                }
        }
        __syncthreads();
    }

    // epilogue: D + bias + residual
#pragma unroll
    for (int mf = 0; mf < 2; mf++) {
        int row = bm + wm + mf * 16 + (lane >> 2);
#pragma unroll
        for (int nf = 0; nf < 4; nf++) {
            int col = bn + wn + nf * 8 + (lane & 3) * 2;
            g_no[row * Dd + col]           = acc[mf][nf][0] + bg[col]     + g_h[row * Dd + col];
            g_no[row * Dd + col + 1]       = acc[mf][nf][1] + bg[col + 1] + g_h[row * Dd + col + 1];
            g_no[(row + 8) * Dd + col]     = acc[mf][nf][2] + bg[col]     + g_h[(row + 8) * Dd + col];
            g_no[(row + 8) * Dd + col + 1] = acc[mf][nf][3] + bg[col + 1] + g_h[(row + 8) * Dd + col + 1];
        }
    }
}

// =================== K6: p = node_output @ W_d ===================
__global__ void k_proj(const float* __restrict__ Wd) {
    int d = blockIdx.x;
    float s = 0.f;
    for (int k = threadIdx.x; k < Dd; k += 256)
        s += g_no[d * Dd + k] * Wd[k];
#pragma unroll
    for (int o = 16; o; o >>= 1) s += __shfl_down_sync(0xffffffff, s, o);
    __shared__ float red[8];
    int lane = threadIdx.x & 31, wid = threadIdx.x >> 5;
    if (lane == 0) red[wid] = s;
    __syncthreads();
    if (wid == 0) {
        s = (lane < 8) ? red[lane] : 0.f;
#pragma unroll
        for (int o = 4; o; o >>= 1) s += __shfl_down_sync(0xffffffff, s, o);
        if (lane == 0) g_p[d] = s;
    }
}

// =================== K7: dis_pred ===================
__global__ void k_dis(float* __restrict__ out, const float* __restrict__ bd) {
    int i = blockIdx.x;
    float pi = g_p[i];
    float b = bd[0];
    for (int j = threadIdx.x; j < Nn; j += blockDim.x) {
        float z = g_p[j] - pi + b;
        out[i * Nn + j] = 1.0f / (1.0f + expf(-z));
    }
}

// =================== K8: mask_pred ===================
__global__ void k_mask(const int* __restrict__ midx, const float* __restrict__ Wm,
                       const float* __restrict__ bm, float* __restrict__ out) {
    int b = blockIdx.x;
    int r = midx[b];
    float s0 = 0.f, s1 = 0.f;
    for (int k = threadIdx.x; k < Dd; k += 128) {
        float v = g_no[r * Dd + k];
        s0 += v * Wm[k * 2 + 0];
        s1 += v * Wm[k * 2 + 1];
    }
    __shared__ float red[2][4];
    int lane = threadIdx.x & 31, wid = threadIdx.x >> 5;
#pragma unroll
    for (int o = 16; o; o >>= 1) {
        s0 += __shfl_down_sync(0xffffffff, s0, o);
        s1 += __shfl_down_sync(0xffffffff, s1, o);
    }
    if (lane == 0) { red[0][wid] = s0; red[1][wid] = s1; }
    __syncthreads();
    if (threadIdx.x == 0) {
        s0 = red[0][0] + red[0][1] + red[0][2] + red[0][3];
        s1 = red[1][0] + red[1][1] + red[1][2] + red[1][3];
        out[Nn * Nn + b * 2 + 0] = tanhf(s0 + bm[0]);
        out[Nn * Nn + b * 2 + 1] = tanhf(s1 + bm[1]);
    }
}

extern "C" void kernel_launch(void* const* d_in, const int* in_sizes, int n_in,
                              void* d_out, int out_size) {
    const float* lm  = (const float*)d_in[0];
    const float* nf  = (const float*)d_in[1];
    const float* ew  = (const float*)d_in[2];
    const int*   src = (const int*)d_in[3];
    const int*   dst = (const int*)d_in[4];
    const int*   mi  = (const int*)d_in[5];
    const float* Wg  = (const float*)d_in[6];
    const float* bg  = (const float*)d_in[7];
    const float* Wd  = (const float*)d_in[8];
    const float* bd  = (const float*)d_in[9];
    const float* Wm  = (const float*)d_in[10];
    const float* bm  = (const float*)d_in[11];
    float* out = (float*)d_out;

    cudaFuncSetAttribute(k_gemm_mma, cudaFuncAttributeMaxDynamicSharedMemorySize,
                         3 * STAGE_B);

    k_build_h<<<(Nn * (Dd / 4) + 255) / 256, 256>>>(lm, nf);
    k_convW<<<dim3(Dd / 32, Dd / 32), 256>>>(Wg);
    k_csr<<<1, Nn>>>(dst);
    k_neigh<<<Nn, 320>>>(src, ew);
    k_gemm_mma<<<dim3(Dd / 64, Nn / 64), 128, 3 * STAGE_B>>>(bg);
    k_proj<<<Nn, 256>>>(Wd);
    k_dis<<<Nn, 256>>>(out, bd);
    k_mask<<<Mm, 128>>>(mi, Wm, bm, out);
}

// round 6
// speedup vs baseline: 1.5277x; 1.0200x over previous
#include <cuda_runtime.h>
#include <cuda_bf16.h>
#include <stdint.h>
#include <math.h>

#define Nn 512
#define Ee 16384
#define Dd 1280
#define LMd 1024
#define NFd 256
#define Mm 64
#define KTOT 3840            // 3*Dd : [hi | hi | lo] x [hi | lo | hi]
#define KC2 64               // K per smem chunk
#define NC2 (KTOT / KC2)     // 60

// ---- device scratch ----
__device__ float g_h[Nn * Dd];
__device__ float g_no[Nn * Dd];
__device__ float g_p[Nn];
__device__ int   g_off[Nn + 1];
__device__ int   g_es[Ee];
__device__ __nv_bfloat16 g_A[Nn * KTOT];     // X split, K-major
__device__ __nv_bfloat16 g_B[Dd * KTOT];     // W^T split, K-major

__device__ __forceinline__ uint32_t smem_u32(const void* p) {
    uint32_t a;
    asm("{ .reg .u64 t; cvta.to.shared.u64 t, %1; cvt.u32.u64 %0, t; }" : "=r"(a) : "l"(p));
    return a;
}
__device__ __forceinline__ uint32_t pack_bf2(float a, float b) {
    __nv_bfloat162 t = __floats2bfloat162_rn(a, b);
    return *(uint32_t*)&t;
}

// =================== K1: build h (float4) ===================
__global__ void k_build_h(const float* __restrict__ lm, const float* __restrict__ nf) {
    int idx = blockIdx.x * blockDim.x + threadIdx.x;
    if (idx >= Nn * (Dd / 4)) return;
    int i = idx / (Dd / 4), j4 = idx - i * (Dd / 4);
    float4 v;
    if (j4 < LMd / 4) v = *(const float4*)(lm + (i + 1) * LMd + 4 * j4);
    else              v = *(const float4*)(nf + i * NFd + 4 * (j4 - LMd / 4));
    *(float4*)(g_h + i * Dd + 4 * j4) = v;
}

// =================== K2: W transpose + bf16 hi/lo split ===================
__global__ void k_convW(const float* __restrict__ W) {
    __shared__ float tile[32][33];
    int n0 = blockIdx.x * 32, k0 = blockIdx.y * 32;
    int tid = threadIdx.x;
    int tx = tid & 31, ty = tid >> 5;
#pragma unroll
    for (int i = 0; i < 4; i++)
        tile[ty + 8 * i][tx] = W[(k0 + ty + 8 * i) * Dd + n0 + tx];
    __syncthreads();
    int p = tid & 15;
    int nr = tid >> 4;
#pragma unroll
    for (int i = 0; i < 2; i++) {
        int nn = nr + 16 * i;
        int n = n0 + nn;
        float v0 = tile[2 * p][nn], v1 = tile[2 * p + 1][nn];
        float h0f = __bfloat162float(__float2bfloat16(v0));
        float h1f = __bfloat162float(__float2bfloat16(v1));
        uint32_t hi2 = pack_bf2(v0, v1);
        uint32_t lo2 = pack_bf2(v0 - h0f, v1 - h1f);
        size_t b = (size_t)n * KTOT + k0 + 2 * p;
        *(uint32_t*)(g_B + b)          = hi2;
        *(uint32_t*)(g_B + b + Dd)     = lo2;
        *(uint32_t*)(g_B + b + 2 * Dd) = hi2;
    }
}

// =================== K3: CSR build (one block) ===================
__global__ void k_csr(const int* __restrict__ dst) {
    __shared__ int cnt[Nn];
    __shared__ int s[Nn];
    __shared__ int pos[Nn];
    int t = threadIdx.x;
    cnt[t] = 0;
    __syncthreads();
    for (int e = t; e < Ee; e += Nn) atomicAdd(&cnt[dst[e]], 1);
    __syncthreads();
    s[t] = cnt[t];
    __syncthreads();
    for (int off = 1; off < Nn; off <<= 1) {
        int v = (t >= off) ? s[t - off] : 0;
        __syncthreads();
        s[t] += v;
        __syncthreads();
    }
    g_off[t + 1] = s[t];
    if (t == 0) g_off[0] = 0;
    pos[t] = s[t] - cnt[t];
    __syncthreads();
    for (int e = t; e < Ee; e += Nn) {
        int d = dst[e];
        int p = atomicAdd(&pos[d], 1);
        g_es[p] = e;
    }
}

// =================== K4: neigh max, unroll x4, write split A ===================
__global__ void k_neigh(const int* __restrict__ src, const float* __restrict__ ew) {
    int d = blockIdx.x;
    int beg = g_off[d], end = g_off[d + 1];
    int t = threadIdx.x;                    // 0..319
    __shared__ int   ss[128];
    __shared__ float sw[128];
    float4 m = make_float4(-INFINITY, -INFINITY, -INFINITY, -INFINITY);

    for (int c = beg; c < end; c += 128) {
        int nc = min(128, end - c);
        if (t < nc) {
            int e = g_es[c + t];
            ss[t] = src[e];
            sw[t] = ew[e];
        }
        __syncthreads();
        int j = 0;
        for (; j + 4 <= nc; j += 4) {
            const float4* h0 = (const float4*)(g_h + ss[j + 0] * Dd);
            const float4* h1 = (const float4*)(g_h + ss[j + 1] * Dd);
            const float4* h2 = (const float4*)(g_h + ss[j + 2] * Dd);
            const float4* h3 = (const float4*)(g_h + ss[j + 3] * Dd);
            float4 v0 = h0[t], v1 = h1[t], v2 = h2[t], v3 = h3[t];
            float w0 = sw[j + 0], w1 = sw[j + 1], w2 = sw[j + 2], w3 = sw[j + 3];
            m.x = fmaxf(fmaxf(m.x, v0.x * w0), fmaxf(v1.x * w1, fmaxf(v2.x * w2, v3.x * w3)));
            m.y = fmaxf(fmaxf(m.y, v0.y * w0), fmaxf(v1.y * w1, fmaxf(v2.y * w2, v3.y * w3)));
            m.z = fmaxf(fmaxf(m.z, v0.z * w0), fmaxf(v1.z * w1, fmaxf(v2.z * w2, v3.z * w3)));
            m.w = fmaxf(fmaxf(m.w, v0.w * w0), fmaxf(v1.w * w1, fmaxf(v2.w * w2, v3.w * w3)));
        }
        for (; j < nc; j++) {
            const float4* hr = (const float4*)(g_h + ss[j] * Dd);
            float w = sw[j];
            float4 v = hr[t];
            m.x = fmaxf(m.x, v.x * w);
            m.y = fmaxf(m.y, v.y * w);
            m.z = fmaxf(m.z, v.z * w);
            m.w = fmaxf(m.w, v.w * w);
        }
        __syncthreads();
    }
    float4 hv = ((const float4*)(g_h + d * Dd))[t];
    float x0 = hv.x + ((m.x == -INFINITY) ? 0.f : m.x);
    float x1 = hv.y + ((m.y == -INFINITY) ? 0.f : m.y);
    float x2 = hv.z + ((m.z == -INFINITY) ? 0.f : m.z);
    float x3 = hv.w + ((m.w == -INFINITY) ? 0.f : m.w);
    float h0 = __bfloat162float(__float2bfloat16(x0));
    float h1 = __bfloat162float(__float2bfloat16(x1));
    float h2 = __bfloat162float(__float2bfloat16(x2));
    float h3 = __bfloat162float(__float2bfloat16(x3));
    uint32_t hiA = pack_bf2(x0, x1), hiB = pack_bf2(x2, x3);
    uint32_t loA = pack_bf2(x0 - h0, x1 - h1), loB = pack_bf2(x2 - h2, x3 - h3);
    size_t ab = (size_t)d * KTOT + 4 * t;
    *(uint32_t*)(g_A + ab) = hiA;              *(uint32_t*)(g_A + ab + 2) = hiB;
    *(uint32_t*)(g_A + ab + Dd) = hiA;         *(uint32_t*)(g_A + ab + Dd + 2) = hiB;
    *(uint32_t*)(g_A + ab + 2 * Dd) = loA;     *(uint32_t*)(g_A + ab + 2 * Dd + 2) = loB;
}

// =================== K5: mma.sync bf16 GEMM, 64x128 tiles, 3-stage, KC=64 ===================
#define SPAD2 72                     // bf16 row stride (144 B)
#define ATILE_B (64 * SPAD2 * 2)     // 9216
#define BTILE_B (128 * SPAD2 * 2)    // 18432
#define STAGE_B (ATILE_B + BTILE_B)  // 27648
__global__ __launch_bounds__(256, 2) void k_gemm_mma(const float* __restrict__ bg) {
    extern __shared__ __align__(16) unsigned char smem[];
    int tid = threadIdx.x;
    int lane = tid & 31, warp = tid >> 5;
    int bm = blockIdx.y * 64, bn = blockIdx.x * 128;
    int wm = (warp & 1) * 32, wn = (warp >> 1) * 32;

    uint32_t sbase = smem_u32(smem);
    uint32_t sA[3], sB[3];
#pragma unroll
    for (int st = 0; st < 3; st++) {
        sA[st] = sbase + st * STAGE_B;
        sB[st] = sA[st] + ATILE_B;
    }

    float acc[2][4][4];
#pragma unroll
    for (int mf = 0; mf < 2; mf++)
#pragma unroll
        for (int nf = 0; nf < 4; nf++)
#pragma unroll
            for (int r = 0; r < 4; r++) acc[mf][nf][r] = 0.f;

    // A tile: 64 rows x 8 segs = 512 chunks -> 2/thread; B: 128x8 = 1024 -> 4/thread
#define LOAD_CHUNK(cidx, st)                                                        \
    do {                                                                            \
        int k0 = (cidx) * KC2;                                                      \
        _Pragma("unroll")                                                           \
        for (int it = 0; it < 2; it++) {                                            \
            int idx = it * 256 + tid;                                               \
            int row = idx >> 3, seg = idx & 7;                                      \
            uint32_t da = sA[st] + row * (SPAD2 * 2) + seg * 16;                    \
            const void* pa = g_A + (size_t)(bm + row) * KTOT + k0 + seg * 8;        \
            asm volatile("cp.async.cg.shared.global [%0], [%1], 16;" :: "r"(da), "l"(pa)); \
        }                                                                           \
        _Pragma("unroll")                                                           \
        for (int it = 0; it < 4; it++) {                                            \
            int idx = it * 256 + tid;                                               \
            int row = idx >> 3, seg = idx & 7;                                      \
            uint32_t db = sB[st] + row * (SPAD2 * 2) + seg * 16;                    \
            const void* pb = g_B + (size_t)(bn + row) * KTOT + k0 + seg * 8;        \
            asm volatile("cp.async.cg.shared.global [%0], [%1], 16;" :: "r"(db), "l"(pb)); \
        }                                                                           \
        asm volatile("cp.async.commit_group;" ::: "memory");                        \
    } while (0)

    LOAD_CHUNK(0, 0);
    LOAD_CHUNK(1, 1);

    for (int c = 0; c < NC2; c++) {
        int st = c % 3;
        if (c + 2 < NC2) {
            LOAD_CHUNK(c + 2, (c + 2) % 3);
            asm volatile("cp.async.wait_group 2;" ::: "memory");
        } else if (c + 1 < NC2) {
            asm volatile("cp.async.wait_group 1;" ::: "memory");
        } else {
            asm volatile("cp.async.wait_group 0;" ::: "memory");
        }
        __syncthreads();

        const uint32_t* A32 = (const uint32_t*)(smem + (size_t)st * STAGE_B);
        const uint32_t* B32 = (const uint32_t*)(smem + (size_t)st * STAGE_B + ATILE_B);
#pragma unroll
        for (int ks = 0; ks < 4; ks++) {
            int ko = ks * 8;
            uint32_t a[2][4];
#pragma unroll
            for (int mf = 0; mf < 2; mf++) {
                int base = (wm + mf * 16 + (lane >> 2)) * (SPAD2 / 2) + (lane & 3) + ko;
                a[mf][0] = A32[base];
                a[mf][1] = A32[base + 8 * (SPAD2 / 2)];
                a[mf][2] = A32[base + 4];
                a[mf][3] = A32[base + 8 * (SPAD2 / 2) + 4];
            }
            uint32_t b[4][2];
#pragma unroll
            for (int nf = 0; nf < 4; nf++) {
                int base = (wn + nf * 8 + (lane >> 2)) * (SPAD2 / 2) + (lane & 3) + ko;
                b[nf][0] = B32[base];
                b[nf][1] = B32[base + 4];
            }
#pragma unroll
            for (int mf = 0; mf < 2; mf++)
#pragma unroll
                for (int nf = 0; nf < 4; nf++) {
                    asm volatile(
                        "mma.sync.aligned.m16n8k16.row.col.f32.bf16.bf16.f32 "
                        "{%0,%1,%2,%3}, {%4,%5,%6,%7}, {%8,%9}, {%0,%1,%2,%3};"
                        : "+f"(acc[mf][nf][0]), "+f"(acc[mf][nf][1]),
                          "+f"(acc[mf][nf][2]), "+f"(acc[mf][nf][3])
                        : "r"(a[mf][0]), "r"(a[mf][1]), "r"(a[mf][2]), "r"(a[mf][3]),
                          "r"(b[nf][0]), "r"(b[nf][1]));
                }
        }
        __syncthreads();
    }

    // epilogue: D + bias + residual
#pragma unroll
    for (int mf = 0; mf < 2; mf++) {
        int row = bm + wm + mf * 16 + (lane >> 2);
#pragma unroll
        for (int nf = 0; nf < 4; nf++) {
            int col = bn + wn + nf * 8 + (lane & 3) * 2;
            g_no[row * Dd + col]           = acc[mf][nf][0] + bg[col]     + g_h[row * Dd + col];
            g_no[row * Dd + col + 1]       = acc[mf][nf][1] + bg[col + 1] + g_h[row * Dd + col + 1];
            g_no[(row + 8) * Dd + col]     = acc[mf][nf][2] + bg[col]     + g_h[(row + 8) * Dd + col];
            g_no[(row + 8) * Dd + col + 1] = acc[mf][nf][3] + bg[col + 1] + g_h[(row + 8) * Dd + col + 1];
        }
    }
}

// =================== K6: p = node_output @ W_d ===================
__global__ void k_proj(const float* __restrict__ Wd) {
    int d = blockIdx.x;
    float s = 0.f;
    for (int k = threadIdx.x; k < Dd; k += 256)
        s += g_no[d * Dd + k] * Wd[k];
#pragma unroll
    for (int o = 16; o; o >>= 1) s += __shfl_down_sync(0xffffffff, s, o);
    __shared__ float red[8];
    int lane = threadIdx.x & 31, wid = threadIdx.x >> 5;
    if (lane == 0) red[wid] = s;
    __syncthreads();
    if (wid == 0) {
        s = (lane < 8) ? red[lane] : 0.f;
#pragma unroll
        for (int o = 4; o; o >>= 1) s += __shfl_down_sync(0xffffffff, s, o);
        if (lane == 0) g_p[d] = s;
    }
}

// =================== K7: dis_pred (float4 stores) ===================
__global__ void k_dis(float* __restrict__ out, const float* __restrict__ bd) {
    __shared__ float ps[Nn];
    int i = blockIdx.x;
    int t = threadIdx.x;   // 128
    ps[t] = g_p[t]; ps[t + 128] = g_p[t + 128];
    ps[t + 256] = g_p[t + 256]; ps[t + 384] = g_p[t + 384];
    __syncthreads();
    float pi = g_p[i];
    float b = bd[0];
    float4 o;
    int j = 4 * t;
    o.x = 1.0f / (1.0f + expf(-(ps[j + 0] - pi + b)));
    o.y = 1.0f / (1.0f + expf(-(ps[j + 1] - pi + b)));
    o.z = 1.0f / (1.0f + expf(-(ps[j + 2] - pi + b)));
    o.w = 1.0f / (1.0f + expf(-(ps[j + 3] - pi + b)));
    *(float4*)(out + i * Nn + j) = o;
}

// =================== K8: mask_pred ===================
__global__ void k_mask(const int* __restrict__ midx, const float* __restrict__ Wm,
                       const float* __restrict__ bm, float* __restrict__ out) {
    int b = blockIdx.x;
    int r = midx[b];
    float s0 = 0.f, s1 = 0.f;
    for (int k = threadIdx.x; k < Dd; k += 128) {
        float v = g_no[r * Dd + k];
        s0 += v * Wm[k * 2 + 0];
        s1 += v * Wm[k * 2 + 1];
    }
    __shared__ float red[2][4];
    int lane = threadIdx.x & 31, wid = threadIdx.x >> 5;
#pragma unroll
    for (int o = 16; o; o >>= 1) {
        s0 += __shfl_down_sync(0xffffffff, s0, o);
        s1 += __shfl_down_sync(0xffffffff, s1, o);
    }
    if (lane == 0) { red[0][wid] = s0; red[1][wid] = s1; }
    __syncthreads();
    if (threadIdx.x == 0) {
        s0 = red[0][0] + red[0][1] + red[0][2] + red[0][3];
        s1 = red[1][0] + red[1][1] + red[1][2] + red[1][3];
        out[Nn * Nn + b * 2 + 0] = tanhf(s0 + bm[0]);
        out[Nn * Nn + b * 2 + 1] = tanhf(s1 + bm[1]);
    }
}

extern "C" void kernel_launch(void* const* d_in, const int* in_sizes, int n_in,
                              void* d_out, int out_size) {
    const float* lm  = (const float*)d_in[0];
    const float* nf  = (const float*)d_in[1];
    const float* ew  = (const float*)d_in[2];
    const int*   src = (const int*)d_in[3];
    const int*   dst = (const int*)d_in[4];
    const int*   mi  = (const int*)d_in[5];
    const float* Wg  = (const float*)d_in[6];
    const float* bg  = (const float*)d_in[7];
    const float* Wd  = (const float*)d_in[8];
    const float* bd  = (const float*)d_in[9];
    const float* Wm  = (const float*)d_in[10];
    const float* bm  = (const float*)d_in[11];
    float* out = (float*)d_out;

    cudaFuncSetAttribute(k_gemm_mma, cudaFuncAttributeMaxDynamicSharedMemorySize,
                         3 * STAGE_B);

    k_build_h<<<(Nn * (Dd / 4) + 255) / 256, 256>>>(lm, nf);
    k_convW<<<dim3(Dd / 32, Dd / 32), 256>>>(Wg);
    k_csr<<<1, Nn>>>(dst);
    k_neigh<<<Nn, 320>>>(src, ew);
    k_gemm_mma<<<dim3(Dd / 128, Nn / 64), 256, 3 * STAGE_B>>>(bg);
    k_proj<<<Nn, 256>>>(Wd);
    k_dis<<<Nn, 128>>>(out, bd);
    k_mask<<<Mm, 128>>>(mi, Wm, bm, out);
}

// round 7
// speedup vs baseline: 1.9457x; 1.2736x over previous
#include <cuda_runtime.h>
#include <cuda_fp16.h>
#include <stdint.h>
#include <math.h>

#define Nn 512
#define Ee 16384
#define Dd 1280
#define LMd 1024
#define NFd 256
#define Mm 64
#define KTOT 2560            // 2*Dd : A=[hi|lo], B=[hi|hi]
#define KC2 64               // K per smem chunk
#define NC2 (KTOT / KC2)     // 40

// ---- device scratch ----
__device__ float g_h[Nn * Dd];
__device__ float g_no[Nn * Dd];
__device__ float g_pp[10 * Nn];       // per-col-block partial projections
__device__ int   g_off[Nn + 1];
__device__ int   g_es[Ee];
__device__ __half g_A[Nn * KTOT];     // X split, K-major
__device__ __half g_B[Dd * KTOT];     // W^T, K-major (hi twice)

__device__ __forceinline__ uint32_t smem_u32(const void* p) {
    uint32_t a;
    asm("{ .reg .u64 t; cvta.to.shared.u64 t, %1; cvt.u32.u64 %0, t; }" : "=r"(a) : "l"(p));
    return a;
}
__device__ __forceinline__ uint32_t pack_h2(float a, float b) {
    __half2 t = __floats2half2_rn(a, b);
    return *(uint32_t*)&t;
}

// =================== K1: fused build_h + convW ===================
#define BH_BLKS 640     // Nn*Dd/4/256
__global__ void k_prep(const float* __restrict__ lm, const float* __restrict__ nf,
                       const float* __restrict__ W) {
    int b = blockIdx.x;
    int tid = threadIdx.x;
    if (b < BH_BLKS) {
        int idx = b * 256 + tid;
        int i = idx / (Dd / 4), j4 = idx - i * (Dd / 4);
        float4 v;
        if (j4 < LMd / 4) v = *(const float4*)(lm + (i + 1) * LMd + 4 * j4);
        else              v = *(const float4*)(nf + i * NFd + 4 * (j4 - LMd / 4));
        *(float4*)(g_h + i * Dd + 4 * j4) = v;
        return;
    }
    // convW: transpose 32x32 tile, fp16 convert, two regions (hi twice)
    int bi = b - BH_BLKS;
    int n0 = (bi % 40) * 32, k0 = (bi / 40) * 32;
    __shared__ float tile[32][33];
    int tx = tid & 31, ty = tid >> 5;
#pragma unroll
    for (int i = 0; i < 4; i++)
        tile[ty + 8 * i][tx] = W[(k0 + ty + 8 * i) * Dd + n0 + tx];
    __syncthreads();
    int p = tid & 15;
    int nr = tid >> 4;
#pragma unroll
    for (int i = 0; i < 2; i++) {
        int nn = nr + 16 * i;
        int n = n0 + nn;
        uint32_t hi2 = pack_h2(tile[2 * p][nn], tile[2 * p + 1][nn]);
        size_t bb = (size_t)n * KTOT + k0 + 2 * p;
        *(uint32_t*)(g_B + bb)      = hi2;
        *(uint32_t*)(g_B + bb + Dd) = hi2;
    }
}

// =================== K2: CSR build (one block, 1024 thr) ===================
__global__ void k_csr(const int* __restrict__ dst) {
    __shared__ int cnt[Nn];
    __shared__ int s[Nn];
    __shared__ int pos[Nn];
    int t = threadIdx.x;
    if (t < Nn) cnt[t] = 0;
    __syncthreads();
    for (int e = t; e < Ee; e += 1024) atomicAdd(&cnt[dst[e]], 1);
    __syncthreads();
    if (t < Nn) s[t] = cnt[t];
    __syncthreads();
    for (int off = 1; off < Nn; off <<= 1) {
        int v = (t >= off && t < Nn) ? s[t - off] : 0;
        __syncthreads();
        if (t < Nn) s[t] += v;
        __syncthreads();
    }
    if (t < Nn) {
        g_off[t + 1] = s[t];
        if (t == 0) g_off[0] = 0;
        pos[t] = s[t] - cnt[t];
    }
    __syncthreads();
    for (int e = t; e < Ee; e += 1024) {
        int d = dst[e];
        int p = atomicAdd(&pos[d], 1);
        g_es[p] = e;
    }
}

// =================== K3: neigh max + write fp16-split A ===================
__global__ void k_neigh(const int* __restrict__ src, const float* __restrict__ ew) {
    int d = blockIdx.x;
    int beg = g_off[d], end = g_off[d + 1];
    int t = threadIdx.x;                    // 0..319
    __shared__ int   ss[128];
    __shared__ float sw[128];
    float4 m = make_float4(-INFINITY, -INFINITY, -INFINITY, -INFINITY);

    for (int c = beg; c < end; c += 128) {
        int nc = min(128, end - c);
        if (t < nc) {
            int e = g_es[c + t];
            ss[t] = src[e];
            sw[t] = ew[e];
        }
        __syncthreads();
        int j = 0;
        for (; j + 4 <= nc; j += 4) {
            const float4* h0 = (const float4*)(g_h + ss[j + 0] * Dd);
            const float4* h1 = (const float4*)(g_h + ss[j + 1] * Dd);
            const float4* h2 = (const float4*)(g_h + ss[j + 2] * Dd);
            const float4* h3 = (const float4*)(g_h + ss[j + 3] * Dd);
            float4 v0 = h0[t], v1 = h1[t], v2 = h2[t], v3 = h3[t];
            float w0 = sw[j + 0], w1 = sw[j + 1], w2 = sw[j + 2], w3 = sw[j + 3];
            m.x = fmaxf(fmaxf(m.x, v0.x * w0), fmaxf(v1.x * w1, fmaxf(v2.x * w2, v3.x * w3)));
            m.y = fmaxf(fmaxf(m.y, v0.y * w0), fmaxf(v1.y * w1, fmaxf(v2.y * w2, v3.y * w3)));
            m.z = fmaxf(fmaxf(m.z, v0.z * w0), fmaxf(v1.z * w1, fmaxf(v2.z * w2, v3.z * w3)));
            m.w = fmaxf(fmaxf(m.w, v0.w * w0), fmaxf(v1.w * w1, fmaxf(v2.w * w2, v3.w * w3)));
        }
        for (; j < nc; j++) {
            const float4* hr = (const float4*)(g_h + ss[j] * Dd);
            float w = sw[j];
            float4 v = hr[t];
            m.x = fmaxf(m.x, v.x * w);
            m.y = fmaxf(m.y, v.y * w);
            m.z = fmaxf(m.z, v.z * w);
            m.w = fmaxf(m.w, v.w * w);
        }
        __syncthreads();
    }
    float4 hv = ((const float4*)(g_h + d * Dd))[t];
    float x0 = hv.x + ((m.x == -INFINITY) ? 0.f : m.x);
    float x1 = hv.y + ((m.y == -INFINITY) ? 0.f : m.y);
    float x2 = hv.z + ((m.z == -INFINITY) ? 0.f : m.z);
    float x3 = hv.w + ((m.w == -INFINITY) ? 0.f : m.w);
    float h0 = __half2float(__float2half_rn(x0));
    float h1 = __half2float(__float2half_rn(x1));
    float h2 = __half2float(__float2half_rn(x2));
    float h3 = __half2float(__float2half_rn(x3));
    uint32_t hiA = pack_h2(x0, x1), hiB = pack_h2(x2, x3);
    uint32_t loA = pack_h2(x0 - h0, x1 - h1), loB = pack_h2(x2 - h2, x3 - h3);
    size_t ab = (size_t)d * KTOT + 4 * t;
    *(uint32_t*)(g_A + ab) = hiA;          *(uint32_t*)(g_A + ab + 2) = hiB;
    *(uint32_t*)(g_A + ab + Dd) = loA;     *(uint32_t*)(g_A + ab + Dd + 2) = loB;
}

// =================== K4: mma.sync fp16 GEMM, 64x128 tiles + proj partials ===================
#define SPAD2 72                     // half row stride (144 B)
#define ATILE_B (64 * SPAD2 * 2)     // 9216
#define BTILE_B (128 * SPAD2 * 2)    // 18432
#define STAGE_B (ATILE_B + BTILE_B)  // 27648
__global__ __launch_bounds__(256, 2) void k_gemm_mma(const float* __restrict__ bg,
                                                     const float* __restrict__ Wd) {
    extern __shared__ __align__(16) unsigned char smem[];
    int tid = threadIdx.x;
    int lane = tid & 31, warp = tid >> 5;
    int bm = blockIdx.y * 64, bn = blockIdx.x * 128;
    int wm = (warp & 1) * 32, wn = (warp >> 1) * 32;

    uint32_t sbase = smem_u32(smem);
    uint32_t sA[3], sB[3];
#pragma unroll
    for (int st = 0; st < 3; st++) {
        sA[st] = sbase + st * STAGE_B;
        sB[st] = sA[st] + ATILE_B;
    }

    float acc[2][4][4];
#pragma unroll
    for (int mf = 0; mf < 2; mf++)
#pragma unroll
        for (int nf = 0; nf < 4; nf++)
#pragma unroll
            for (int r = 0; r < 4; r++) acc[mf][nf][r] = 0.f;

#define LOAD_CHUNK(cidx, st)                                                        \
    do {                                                                            \
        int k0 = (cidx) * KC2;                                                      \
        _Pragma("unroll")                                                           \
        for (int it = 0; it < 2; it++) {                                            \
            int idx = it * 256 + tid;                                               \
            int row = idx >> 3, seg = idx & 7;                                      \
            uint32_t da = sA[st] + row * (SPAD2 * 2) + seg * 16;                    \
            const void* pa = g_A + (size_t)(bm + row) * KTOT + k0 + seg * 8;        \
            asm volatile("cp.async.cg.shared.global [%0], [%1], 16;" :: "r"(da), "l"(pa)); \
        }                                                                           \
        _Pragma("unroll")                                                           \
        for (int it = 0; it < 4; it++) {                                            \
            int idx = it * 256 + tid;                                               \
            int row = idx >> 3, seg = idx & 7;                                      \
            uint32_t db = sB[st] + row * (SPAD2 * 2) + seg * 16;                    \
            const void* pb = g_B + (size_t)(bn + row) * KTOT + k0 + seg * 8;        \
            asm volatile("cp.async.cg.shared.global [%0], [%1], 16;" :: "r"(db), "l"(pb)); \
        }                                                                           \
        asm volatile("cp.async.commit_group;" ::: "memory");                        \
    } while (0)

    LOAD_CHUNK(0, 0);
    LOAD_CHUNK(1, 1);

    for (int c = 0; c < NC2; c++) {
        int st = c % 3;
        if (c + 2 < NC2) {
            LOAD_CHUNK(c + 2, (c + 2) % 3);
            asm volatile("cp.async.wait_group 2;" ::: "memory");
        } else if (c + 1 < NC2) {
            asm volatile("cp.async.wait_group 1;" ::: "memory");
        } else {
            asm volatile("cp.async.wait_group 0;" ::: "memory");
        }
        __syncthreads();

        const uint32_t* A32 = (const uint32_t*)(smem + (size_t)st * STAGE_B);
        const uint32_t* B32 = (const uint32_t*)(smem + (size_t)st * STAGE_B + ATILE_B);
#pragma unroll
        for (int ks = 0; ks < 4; ks++) {
            int ko = ks * 8;
            uint32_t a[2][4];
#pragma unroll
            for (int mf = 0; mf < 2; mf++) {
                int base = (wm + mf * 16 + (lane >> 2)) * (SPAD2 / 2) + (lane & 3) + ko;
                a[mf][0] = A32[base];
                a[mf][1] = A32[base + 8 * (SPAD2 / 2)];
                a[mf][2] = A32[base + 4];
                a[mf][3] = A32[base + 8 * (SPAD2 / 2) + 4];
            }
            uint32_t b[4][2];
#pragma unroll
            for (int nf = 0; nf < 4; nf++) {
                int base = (wn + nf * 8 + (lane >> 2)) * (SPAD2 / 2) + (lane & 3) + ko;
                b[nf][0] = B32[base];
                b[nf][1] = B32[base + 4];
            }
#pragma unroll
            for (int mf = 0; mf < 2; mf++)
#pragma unroll
                for (int nf = 0; nf < 4; nf++) {
                    asm volatile(
                        "mma.sync.aligned.m16n8k16.row.col.f32.f16.f16.f32 "
                        "{%0,%1,%2,%3}, {%4,%5,%6,%7}, {%8,%9}, {%0,%1,%2,%3};"
                        : "+f"(acc[mf][nf][0]), "+f"(acc[mf][nf][1]),
                          "+f"(acc[mf][nf][2]), "+f"(acc[mf][nf][3])
                        : "r"(a[mf][0]), "r"(a[mf][1]), "r"(a[mf][2]), "r"(a[mf][3]),
                          "r"(b[nf][0]), "r"(b[nf][1]));
                }
        }
        __syncthreads();
    }

    // epilogue: D + bias + residual -> g_no, plus deterministic proj partials
    float* pb = (float*)smem;   // [64][17], stage buffers dead
#pragma unroll
    for (int mf = 0; mf < 2; mf++) {
        int rl = wm + mf * 16 + (lane >> 2);
        int row = bm + rl;
        float ppa = 0.f, ppb = 0.f;
#pragma unroll
        for (int nf = 0; nf < 4; nf++) {
            int col = bn + wn + nf * 8 + (lane & 3) * 2;
            float v00 = acc[mf][nf][0] + bg[col]     + g_h[row * Dd + col];
            float v01 = acc[mf][nf][1] + bg[col + 1] + g_h[row * Dd + col + 1];
            float v10 = acc[mf][nf][2] + bg[col]     + g_h[(row + 8) * Dd + col];
            float v11 = acc[mf][nf][3] + bg[col + 1] + g_h[(row + 8) * Dd + col + 1];
            g_no[row * Dd + col]           = v00;
            g_no[row * Dd + col + 1]       = v01;
            g_no[(row + 8) * Dd + col]     = v10;
            g_no[(row + 8) * Dd + col + 1] = v11;
            float w0 = Wd[col], w1 = Wd[col + 1];
            ppa += v00 * w0 + v01 * w1;
            ppb += v10 * w0 + v11 * w1;
        }
        int slot = (warp >> 1) * 4 + (lane & 3);
        pb[rl * 17 + slot]       = ppa;
        pb[(rl + 8) * 17 + slot] = ppb;
    }
    __syncthreads();
    if (tid < 64) {
        float s = 0.f;
#pragma unroll
        for (int q = 0; q < 16; q++) s += pb[tid * 17 + q];
        g_pp[blockIdx.x * Nn + bm + tid] = s;
    }
}

// =================== K5: fused dis_pred + mask_pred ===================
__global__ void k_dismask(float* __restrict__ out, const float* __restrict__ bd,
                          const int* __restrict__ midx, const float* __restrict__ Wm,
                          const float* __restrict__ bm) {
    int t = threadIdx.x;   // 128
    if (blockIdx.x < Nn) {
        int i = blockIdx.x;
        __shared__ float ps[Nn];
        for (int jj = t; jj < Nn; jj += 128) {
            float s = 0.f;
#pragma unroll
            for (int c = 0; c < 10; c++) s += g_pp[c * Nn + jj];
            ps[jj] = s;
        }
        __syncthreads();
        float pi = ps[i];
        float b = bd[0];
        int j = 4 * t;
        float4 o;
        o.x = 1.0f / (1.0f + expf(-(ps[j + 0] - pi + b)));
        o.y = 1.0f / (1.0f + expf(-(ps[j + 1] - pi + b)));
        o.z = 1.0f / (1.0f + expf(-(ps[j + 2] - pi + b)));
        o.w = 1.0f / (1.0f + expf(-(ps[j + 3] - pi + b)));
        *(float4*)(out + i * Nn + j) = o;
    } else {
        int b = blockIdx.x - Nn;
        int r = midx[b];
        float s0 = 0.f, s1 = 0.f;
        for (int k = t; k < Dd; k += 128) {
            float v = g_no[r * Dd + k];
            s0 += v * Wm[k * 2 + 0];
            s1 += v * Wm[k * 2 + 1];
        }
        __shared__ float red[2][4];
        int lane = t & 31, wid = t >> 5;
#pragma unroll
        for (int o = 16; o; o >>= 1) {
            s0 += __shfl_down_sync(0xffffffff, s0, o);
            s1 += __shfl_down_sync(0xffffffff, s1, o);
        }
        if (lane == 0) { red[0][wid] = s0; red[1][wid] = s1; }
        __syncthreads();
        if (t == 0) {
            s0 = red[0][0] + red[0][1] + red[0][2] + red[0][3];
            s1 = red[1][0] + red[1][1] + red[1][2] + red[1][3];
            out[Nn * Nn + b * 2 + 0] = tanhf(s0 + bm[0]);
            out[Nn * Nn + b * 2 + 1] = tanhf(s1 + bm[1]);
        }
    }
}

extern "C" void kernel_launch(void* const* d_in, const int* in_sizes, int n_in,
                              void* d_out, int out_size) {
    const float* lm  = (const float*)d_in[0];
    const float* nf  = (const float*)d_in[1];
    const float* ew  = (const float*)d_in[2];
    const int*   src = (const int*)d_in[3];
    const int*   dst = (const int*)d_in[4];
    const int*   mi  = (const int*)d_in[5];
    const float* Wg  = (const float*)d_in[6];
    const float* bg  = (const float*)d_in[7];
    const float* Wd  = (const float*)d_in[8];
    const float* bd  = (const float*)d_in[9];
    const float* Wm  = (const float*)d_in[10];
    const float* bm  = (const float*)d_in[11];
    float* out = (float*)d_out;

    cudaFuncSetAttribute(k_gemm_mma, cudaFuncAttributeMaxDynamicSharedMemorySize,
                         3 * STAGE_B);

    k_prep<<<BH_BLKS + 1600, 256>>>(lm, nf, Wg);
    k_csr<<<1, 1024>>>(dst);
    k_neigh<<<Nn, 320>>>(src, ew);
    k_gemm_mma<<<dim3(Dd / 128, Nn / 64), 256, 3 * STAGE_B>>>(bg, Wd);
    k_dismask<<<Nn + Mm, 128>>>(out, bd, mi, Wm, bm);
}

// round 9
// speedup vs baseline: 2.3205x; 1.1927x over previous
#include <cuda_runtime.h>
#include <cuda_fp16.h>
#include <stdint.h>
#include <math.h>

#define Nn 512
#define Ee 16384
#define Dd 1280
#define LMd 1024
#define NFd 256
#define Mm 64
#define KTOT 2560            // 2*Dd : A=[hi|lo], B=[hi|hi]
#define KC2 64               // K per smem chunk
#define KZC 20               // chunks per split-K half (1280/64)

// ---- device scratch ----
__device__ float g_h[Nn * Dd];
__device__ float g_no[Nn * Dd];
__device__ float g_part[2 * Nn * Dd];
__device__ float g_p[Nn];
__device__ int   g_off[Nn + 1];
__device__ int   g_es[Ee];
__device__ __half g_A[Nn * KTOT];
__device__ __half g_B[Dd * KTOT];

__device__ __forceinline__ uint32_t smem_u32(const void* p) {
    uint32_t a;
    asm("{ .reg .u64 t; cvta.to.shared.u64 t, %1; cvt.u32.u64 %0, t; }" : "=r"(a) : "l"(p));
    return a;
}
__device__ __forceinline__ uint32_t pack_h2(float a, float b) {
    __half2 t = __floats2half2_rn(a, b);
    return *(uint32_t*)&t;
}
#define LDSM4(d0, d1, d2, d3, addr)                                          \
    asm volatile("ldmatrix.sync.aligned.m8n8.x4.shared.b16 {%0,%1,%2,%3}, [%4];" \
                 : "=r"(d0), "=r"(d1), "=r"(d2), "=r"(d3) : "r"(addr))
#define LDSM2(d0, d1, addr)                                                  \
    asm volatile("ldmatrix.sync.aligned.m8n8.x2.shared.b16 {%0,%1}, [%2];"   \
                 : "=r"(d0), "=r"(d1) : "r"(addr))

// =================== K1: fused build_h + convW ===================
#define BH_BLKS 640
__global__ void k_prep(const float* __restrict__ lm, const float* __restrict__ nf,
                       const float* __restrict__ W) {
    int b = blockIdx.x;
    int tid = threadIdx.x;
    if (b < BH_BLKS) {
        int idx = b * 256 + tid;
        int i = idx / (Dd / 4), j4 = idx - i * (Dd / 4);
        float4 v;
        if (j4 < LMd / 4) v = *(const float4*)(lm + (i + 1) * LMd + 4 * j4);
        else              v = *(const float4*)(nf + i * NFd + 4 * (j4 - LMd / 4));
        *(float4*)(g_h + i * Dd + 4 * j4) = v;
        return;
    }
    int bi = b - BH_BLKS;
    int n0 = (bi % 40) * 32, k0 = (bi / 40) * 32;
    __shared__ float tile[32][33];
    int tx = tid & 31, ty = tid >> 5;
#pragma unroll
    for (int i = 0; i < 4; i++)
        tile[ty + 8 * i][tx] = W[(k0 + ty + 8 * i) * Dd + n0 + tx];
    __syncthreads();
    int p = tid & 15;
    int nr = tid >> 4;
#pragma unroll
    for (int i = 0; i < 2; i++) {
        int nn = nr + 16 * i;
        int n = n0 + nn;
        uint32_t hi2 = pack_h2(tile[2 * p][nn], tile[2 * p + 1][nn]);
        size_t bb = (size_t)n * KTOT + k0 + 2 * p;
        *(uint32_t*)(g_B + bb)      = hi2;
        *(uint32_t*)(g_B + bb + Dd) = hi2;
    }
}

// =================== K2: CSR build ===================
__global__ void k_csr(const int* __restrict__ dst) {
    __shared__ int cnt[Nn];
    __shared__ int s[Nn];
    __shared__ int pos[Nn];
    int t = threadIdx.x;
    if (t < Nn) cnt[t] = 0;
    __syncthreads();
    for (int e = t; e < Ee; e += 1024) atomicAdd(&cnt[dst[e]], 1);
    __syncthreads();
    if (t < Nn) s[t] = cnt[t];
    __syncthreads();
    for (int off = 1; off < Nn; off <<= 1) {
        int v = (t >= off && t < Nn) ? s[t - off] : 0;
        __syncthreads();
        if (t < Nn) s[t] += v;
        __syncthreads();
    }
    if (t < Nn) {
        g_off[t + 1] = s[t];
        if (t == 0) g_off[0] = 0;
        pos[t] = s[t] - cnt[t];
    }
    __syncthreads();
    for (int e = t; e < Ee; e += 1024) {
        int d = dst[e];
        int p = atomicAdd(&pos[d], 1);
        g_es[p] = e;
    }
}

// =================== K3: neigh max + write fp16-split A ===================
__global__ void k_neigh(const int* __restrict__ src, const float* __restrict__ ew) {
    int d = blockIdx.x;
    int beg = g_off[d], end = g_off[d + 1];
    int t = threadIdx.x;
    __shared__ int   ss[128];
    __shared__ float sw[128];
    float4 m = make_float4(-INFINITY, -INFINITY, -INFINITY, -INFINITY);

    for (int c = beg; c < end; c += 128) {
        int nc = min(128, end - c);
        if (t < nc) {
            int e = g_es[c + t];
            ss[t] = src[e];
            sw[t] = ew[e];
        }
        __syncthreads();
        int j = 0;
        for (; j + 4 <= nc; j += 4) {
            const float4* h0 = (const float4*)(g_h + ss[j + 0] * Dd);
            const float4* h1 = (const float4*)(g_h + ss[j + 1] * Dd);
            const float4* h2 = (const float4*)(g_h + ss[j + 2] * Dd);
            const float4* h3 = (const float4*)(g_h + ss[j + 3] * Dd);
            float4 v0 = h0[t], v1 = h1[t], v2 = h2[t], v3 = h3[t];
            float w0 = sw[j + 0], w1 = sw[j + 1], w2 = sw[j + 2], w3 = sw[j + 3];
            m.x = fmaxf(fmaxf(m.x, v0.x * w0), fmaxf(v1.x * w1, fmaxf(v2.x * w2, v3.x * w3)));
            m.y = fmaxf(fmaxf(m.y, v0.y * w0), fmaxf(v1.y * w1, fmaxf(v2.y * w2, v3.y * w3)));
            m.z = fmaxf(fmaxf(m.z, v0.z * w0), fmaxf(v1.z * w1, fmaxf(v2.z * w2, v3.z * w3)));
            m.w = fmaxf(fmaxf(m.w, v0.w * w0), fmaxf(v1.w * w1, fmaxf(v2.w * w2, v3.w * w3)));
        }
        for (; j < nc; j++) {
            const float4* hr = (const float4*)(g_h + ss[j] * Dd);
            float w = sw[j];
            float4 v = hr[t];
            m.x = fmaxf(m.x, v.x * w);
            m.y = fmaxf(m.y, v.y * w);
            m.z = fmaxf(m.z, v.z * w);
            m.w = fmaxf(m.w, v.w * w);
        }
        __syncthreads();
    }
    float4 hv = ((const float4*)(g_h + d * Dd))[t];
    float x0 = hv.x + ((m.x == -INFINITY) ? 0.f : m.x);
    float x1 = hv.y + ((m.y == -INFINITY) ? 0.f : m.y);
    float x2 = hv.z + ((m.z == -INFINITY) ? 0.f : m.z);
    float x3 = hv.w + ((m.w == -INFINITY) ? 0.f : m.w);
    float h0 = __half2float(__float2half_rn(x0));
    float h1 = __half2float(__float2half_rn(x1));
    float h2 = __half2float(__float2half_rn(x2));
    float h3 = __half2float(__float2half_rn(x3));
    uint32_t hiA = pack_h2(x0, x1), hiB = pack_h2(x2, x3);
    uint32_t loA = pack_h2(x0 - h0, x1 - h1), loB = pack_h2(x2 - h2, x3 - h3);
    size_t ab = (size_t)d * KTOT + 4 * t;
    *(uint32_t*)(g_A + ab) = hiA;          *(uint32_t*)(g_A + ab + 2) = hiB;
    *(uint32_t*)(g_A + ab + Dd) = loA;     *(uint32_t*)(g_A + ab + Dd + 2) = loB;
}

// =================== K4: split-K fp16 GEMM, 64x64, ldmatrix ===================
#define ROWB 144                   // bytes per smem row (72 halves)
#define ATILE_B (64 * ROWB)        // 9216
#define STAGE_B (2 * ATILE_B)      // 18432
__global__ __launch_bounds__(128, 2) void k_gemm_mma() {
    extern __shared__ __align__(16) unsigned char smem[];
    int tid = threadIdx.x;
    int lane = tid & 31, warp = tid >> 5;
    int bm = blockIdx.y * 64, bn = blockIdx.x * 64;
    int kz = blockIdx.z;
    int wm = (warp & 1) * 32, wn = (warp >> 1) * 32;

    uint32_t sbase = smem_u32(smem);
    uint32_t sA[3], sB[3];
#pragma unroll
    for (int st = 0; st < 3; st++) {
        sA[st] = sbase + st * STAGE_B;
        sB[st] = sA[st] + ATILE_B;
    }

    // ldmatrix lane addresses (byte offsets inside tile)
    uint32_t aoff = (uint32_t)(wm + ((lane & 8) ? 8 : 0) + (lane & 7)) * ROWB
                  + ((lane & 16) ? 16 : 0);
    int lb = lane & 15;
    uint32_t boff = (uint32_t)(wn + (lb & 7)) * ROWB + ((lb & 8) ? 16 : 0);

    float acc[2][4][4];
#pragma unroll
    for (int mf = 0; mf < 2; mf++)
#pragma unroll
        for (int nf = 0; nf < 4; nf++)
#pragma unroll
            for (int r = 0; r < 4; r++) acc[mf][nf][r] = 0.f;

#define LOAD_CHUNK(cidx, st)                                                        \
    do {                                                                            \
        int k0 = kz * (KZC * KC2) + (cidx) * KC2;                                   \
        _Pragma("unroll")                                                           \
        for (int it = 0; it < 4; it++) {                                            \
            int idx = it * 128 + tid;                                               \
            int row = idx >> 3, seg = idx & 7;                                      \
            uint32_t da = sA[st] + row * ROWB + seg * 16;                           \
            uint32_t db = sB[st] + row * ROWB + seg * 16;                           \
            const void* pa = g_A + (size_t)(bm + row) * KTOT + k0 + seg * 8;        \
            const void* pb = g_B + (size_t)(bn + row) * KTOT + k0 + seg * 8;        \
            asm volatile("cp.async.cg.shared.global [%0], [%1], 16;" :: "r"(da), "l"(pa)); \
            asm volatile("cp.async.cg.shared.global [%0], [%1], 16;" :: "r"(db), "l"(pb)); \
        }                                                                           \
        asm volatile("cp.async.commit_group;" ::: "memory");                        \
    } while (0)

    LOAD_CHUNK(0, 0);
    LOAD_CHUNK(1, 1);

    for (int c = 0; c < KZC; c++) {
        int st = c % 3;
        if (c + 2 < KZC) {
            LOAD_CHUNK(c + 2, (c + 2) % 3);
            asm volatile("cp.async.wait_group 2;" ::: "memory");
        } else if (c + 1 < KZC) {
            asm volatile("cp.async.wait_group 1;" ::: "memory");
        } else {
            asm volatile("cp.async.wait_group 0;" ::: "memory");
        }
        __syncthreads();

        uint32_t aB = sA[st] + aoff;
        uint32_t bB = sB[st] + boff;
#pragma unroll
        for (int ks = 0; ks < 4; ks++) {
            // each k16 step spans 32 bytes of the row (two 16B ldmatrix halves)
            uint32_t a[2][4];
            LDSM4(a[0][0], a[0][1], a[0][2], a[0][3], aB + ks * 32);
            LDSM4(a[1][0], a[1][1], a[1][2], a[1][3], aB + 16 * ROWB + ks * 32);
            uint32_t b[4][2];
#pragma unroll
            for (int nf = 0; nf < 4; nf++)
                LDSM2(b[nf][0], b[nf][1], bB + nf * 8 * ROWB + ks * 32);
#pragma unroll
            for (int mf = 0; mf < 2; mf++)
#pragma unroll
                for (int nf = 0; nf < 4; nf++) {
                    asm volatile(
                        "mma.sync.aligned.m16n8k16.row.col.f32.f16.f16.f32 "
                        "{%0,%1,%2,%3}, {%4,%5,%6,%7}, {%8,%9}, {%0,%1,%2,%3};"
                        : "+f"(acc[mf][nf][0]), "+f"(acc[mf][nf][1]),
                          "+f"(acc[mf][nf][2]), "+f"(acc[mf][nf][3])
                        : "r"(a[mf][0]), "r"(a[mf][1]), "r"(a[mf][2]), "r"(a[mf][3]),
                          "r"(b[nf][0]), "r"(b[nf][1]));
                }
        }
        __syncthreads();
    }

    // store raw partials
    float* dst = g_part + (size_t)kz * Nn * Dd;
#pragma unroll
    for (int mf = 0; mf < 2; mf++) {
        int row = bm + wm + mf * 16 + (lane >> 2);
#pragma unroll
        for (int nf = 0; nf < 4; nf++) {
            int col = bn + wn + nf * 8 + (lane & 3) * 2;
            *(float2*)(dst + row * Dd + col)       = make_float2(acc[mf][nf][0], acc[mf][nf][1]);
            *(float2*)(dst + (row + 8) * Dd + col) = make_float2(acc[mf][nf][2], acc[mf][nf][3]);
        }
    }
}

// =================== K5: combine partials + bias + residual + proj ===================
__global__ void k_post(const float* __restrict__ bg, const float* __restrict__ Wd) {
    int row = blockIdx.x;
    int t = threadIdx.x;   // 320
    int c = 4 * t;
    float4 p0 = *(const float4*)(g_part + (size_t)row * Dd + c);
    float4 p1 = *(const float4*)(g_part + (size_t)Nn * Dd + (size_t)row * Dd + c);
    float4 hb = *(const float4*)(g_h + (size_t)row * Dd + c);
    float4 bv = *(const float4*)(bg + c);
    float4 v;
    v.x = p0.x + p1.x + bv.x + hb.x;
    v.y = p0.y + p1.y + bv.y + hb.y;
    v.z = p0.z + p1.z + bv.z + hb.z;
    v.w = p0.w + p1.w + bv.w + hb.w;
    *(float4*)(g_no + (size_t)row * Dd + c) = v;
    float4 wv = *(const float4*)(Wd + c);
    float s = v.x * wv.x + v.y * wv.y + v.z * wv.z + v.w * wv.w;
#pragma unroll
    for (int o = 16; o; o >>= 1) s += __shfl_down_sync(0xffffffff, s, o);
    __shared__ float red[10];
    int lane = t & 31, wid = t >> 5;
    if (lane == 0) red[wid] = s;
    __syncthreads();
    if (t == 0) {
        float tot = 0.f;
#pragma unroll
        for (int q = 0; q < 10; q++) tot += red[q];
        g_p[row] = tot;
    }
}

// =================== K6: fused dis_pred + mask_pred ===================
__global__ void k_dismask(float* __restrict__ out, const float* __restrict__ bd,
                          const int* __restrict__ midx, const float* __restrict__ Wm,
                          const float* __restrict__ bm) {
    int t = threadIdx.x;   // 128
    if (blockIdx.x < Nn) {
        int i = blockIdx.x;
        __shared__ float ps[Nn];
        ps[t] = g_p[t]; ps[t + 128] = g_p[t + 128];
        ps[t + 256] = g_p[t + 256]; ps[t + 384] = g_p[t + 384];
        __syncthreads();
        float pi = ps[i];
        float b = bd[0];
        int j = 4 * t;
        float4 o;
        o.x = 1.0f / (1.0f + expf(-(ps[j + 0] - pi + b)));
        o.y = 1.0f / (1.0f + expf(-(ps[j + 1] - pi + b)));
        o.z = 1.0f / (1.0f + expf(-(ps[j + 2] - pi + b)));
        o.w = 1.0f / (1.0f + expf(-(ps[j + 3] - pi + b)));
        *(float4*)(out + i * Nn + j) = o;
    } else {
        int b = blockIdx.x - Nn;
        int r = midx[b];
        float s0 = 0.f, s1 = 0.f;
        for (int k = t; k < Dd; k += 128) {
            float v = g_no[r * Dd + k];
            s0 += v * Wm[k * 2 + 0];
            s1 += v * Wm[k * 2 + 1];
        }
        __shared__ float red[2][4];
        int lane = t & 31, wid = t >> 5;
#pragma unroll
        for (int o = 16; o; o >>= 1) {
            s0 += __shfl_down_sync(0xffffffff, s0, o);
            s1 += __shfl_down_sync(0xffffffff, s1, o);
        }
        if (lane == 0) { red[0][wid] = s0; red[1][wid] = s1; }
        __syncthreads();
        if (t == 0) {
            s0 = red[0][0] + red[0][1] + red[0][2] + red[0][3];
            s1 = red[1][0] + red[1][1] + red[1][2] + red[1][3];
            out[Nn * Nn + b * 2 + 0] = tanhf(s0 + bm[0]);
            out[Nn * Nn + b * 2 + 1] = tanhf(s1 + bm[1]);
        }
    }
}

extern "C" void kernel_launch(void* const* d_in, const int* in_sizes, int n_in,
                              void* d_out, int out_size) {
    const float* lm  = (const float*)d_in[0];
    const float* nf  = (const float*)d_in[1];
    const float* ew  = (const float*)d_in[2];
    const int*   src = (const int*)d_in[3];
    const int*   dst = (const int*)d_in[4];
    const int*   mi  = (const int*)d_in[5];
    const float* Wg  = (const float*)d_in[6];
    const float* bg  = (const float*)d_in[7];
    const float* Wd  = (const float*)d_in[8];
    const float* bd  = (const float*)d_in[9];
    const float* Wm  = (const float*)d_in[10];
    const float* bm  = (const float*)d_in[11];
    float* out = (float*)d_out;

    cudaFuncSetAttribute(k_gemm_mma, cudaFuncAttributeMaxDynamicSharedMemorySize,
                         3 * STAGE_B);

    k_prep<<<BH_BLKS + 1600, 256>>>(lm, nf, Wg);
    k_csr<<<1, 1024>>>(dst);
    k_neigh<<<Nn, 320>>>(src, ew);
    k_gemm_mma<<<dim3(Dd / 64, Nn / 64, 2), 128, 3 * STAGE_B>>>();
    k_post<<<Nn, 320>>>(bg, Wd);
    k_dismask<<<Nn + Mm, 128>>>(out, bd, mi, Wm, bm);
}

// round 10
// speedup vs baseline: 2.5059x; 1.0799x over previous
#include <cuda_runtime.h>
#include <cuda_fp16.h>
#include <stdint.h>
#include <math.h>

#define Nn 512
#define Ee 16384
#define Dd 1280
#define LMd 1024
#define NFd 256
#define Mm 64
#define KTOT 2560            // 2*Dd : A=[hi|lo], B=[hi|hi]
#define KC2 64               // K per smem chunk
#define NSPLIT 4
#define KZC 10               // chunks per split-K quarter (2560/4/64)

// ---- device scratch ----
__device__ float g_h[Nn * Dd];
__device__ float g_no[Nn * Dd];
__device__ float g_part[NSPLIT * Nn * Dd];
__device__ float g_p[Nn];
__device__ int   g_off[Nn + 1];
__device__ int   g_es[Ee];
__device__ __half g_A[Nn * KTOT];
__device__ __half g_B[Dd * KTOT];

__device__ __forceinline__ uint32_t smem_u32(const void* p) {
    uint32_t a;
    asm("{ .reg .u64 t; cvta.to.shared.u64 t, %1; cvt.u32.u64 %0, t; }" : "=r"(a) : "l"(p));
    return a;
}
__device__ __forceinline__ uint32_t pack_h2(float a, float b) {
    __half2 t = __floats2half2_rn(a, b);
    return *(uint32_t*)&t;
}
#define LDSM4(d0, d1, d2, d3, addr)                                          \
    asm volatile("ldmatrix.sync.aligned.m8n8.x4.shared.b16 {%0,%1,%2,%3}, [%4];" \
                 : "=r"(d0), "=r"(d1), "=r"(d2), "=r"(d3) : "r"(addr))
#define LDSM2(d0, d1, addr)                                                  \
    asm volatile("ldmatrix.sync.aligned.m8n8.x2.shared.b16 {%0,%1}, [%2];"   \
                 : "=r"(d0), "=r"(d1) : "r"(addr))

// =================== K1: fused build_h + convW ===================
#define BH_BLKS 640
__global__ void k_prep(const float* __restrict__ lm, const float* __restrict__ nf,
                       const float* __restrict__ W) {
    int b = blockIdx.x;
    int tid = threadIdx.x;
    if (b < BH_BLKS) {
        int idx = b * 256 + tid;
        int i = idx / (Dd / 4), j4 = idx - i * (Dd / 4);
        float4 v;
        if (j4 < LMd / 4) v = *(const float4*)(lm + (i + 1) * LMd + 4 * j4);
        else              v = *(const float4*)(nf + i * NFd + 4 * (j4 - LMd / 4));
        *(float4*)(g_h + i * Dd + 4 * j4) = v;
        return;
    }
    int bi = b - BH_BLKS;
    int n0 = (bi % 40) * 32, k0 = (bi / 40) * 32;
    __shared__ float tile[32][33];
    int tx = tid & 31, ty = tid >> 5;
#pragma unroll
    for (int i = 0; i < 4; i++)
        tile[ty + 8 * i][tx] = W[(k0 + ty + 8 * i) * Dd + n0 + tx];
    __syncthreads();
    int p = tid & 15;
    int nr = tid >> 4;
#pragma unroll
    for (int i = 0; i < 2; i++) {
        int nn = nr + 16 * i;
        int n = n0 + nn;
        uint32_t hi2 = pack_h2(tile[2 * p][nn], tile[2 * p + 1][nn]);
        size_t bb = (size_t)n * KTOT + k0 + 2 * p;
        *(uint32_t*)(g_B + bb)      = hi2;
        *(uint32_t*)(g_B + bb + Dd) = hi2;
    }
}

// =================== K2: CSR build ===================
__global__ void k_csr(const int* __restrict__ dst) {
    __shared__ int cnt[Nn];
    __shared__ int s[Nn];
    __shared__ int pos[Nn];
    int t = threadIdx.x;
    if (t < Nn) cnt[t] = 0;
    __syncthreads();
    for (int e = t; e < Ee; e += 1024) atomicAdd(&cnt[dst[e]], 1);
    __syncthreads();
    if (t < Nn) s[t] = cnt[t];
    __syncthreads();
    for (int off = 1; off < Nn; off <<= 1) {
        int v = (t >= off && t < Nn) ? s[t - off] : 0;
        __syncthreads();
        if (t < Nn) s[t] += v;
        __syncthreads();
    }
    if (t < Nn) {
        g_off[t + 1] = s[t];
        if (t == 0) g_off[0] = 0;
        pos[t] = s[t] - cnt[t];
    }
    __syncthreads();
    for (int e = t; e < Ee; e += 1024) {
        int d = dst[e];
        int p = atomicAdd(&pos[d], 1);
        g_es[p] = e;
    }
}

// =================== K3: neigh max + write fp16-split A ===================
__global__ void k_neigh(const int* __restrict__ src, const float* __restrict__ ew) {
    int d = blockIdx.x;
    int beg = g_off[d], end = g_off[d + 1];
    int t = threadIdx.x;
    __shared__ int   ss[128];
    __shared__ float sw[128];
    float4 m = make_float4(-INFINITY, -INFINITY, -INFINITY, -INFINITY);

    for (int c = beg; c < end; c += 128) {
        int nc = min(128, end - c);
        if (t < nc) {
            int e = g_es[c + t];
            ss[t] = src[e];
            sw[t] = ew[e];
        }
        __syncthreads();
        int j = 0;
        for (; j + 4 <= nc; j += 4) {
            const float4* h0 = (const float4*)(g_h + ss[j + 0] * Dd);
            const float4* h1 = (const float4*)(g_h + ss[j + 1] * Dd);
            const float4* h2 = (const float4*)(g_h + ss[j + 2] * Dd);
            const float4* h3 = (const float4*)(g_h + ss[j + 3] * Dd);
            float4 v0 = h0[t], v1 = h1[t], v2 = h2[t], v3 = h3[t];
            float w0 = sw[j + 0], w1 = sw[j + 1], w2 = sw[j + 2], w3 = sw[j + 3];
            m.x = fmaxf(fmaxf(m.x, v0.x * w0), fmaxf(v1.x * w1, fmaxf(v2.x * w2, v3.x * w3)));
            m.y = fmaxf(fmaxf(m.y, v0.y * w0), fmaxf(v1.y * w1, fmaxf(v2.y * w2, v3.y * w3)));
            m.z = fmaxf(fmaxf(m.z, v0.z * w0), fmaxf(v1.z * w1, fmaxf(v2.z * w2, v3.z * w3)));
            m.w = fmaxf(fmaxf(m.w, v0.w * w0), fmaxf(v1.w * w1, fmaxf(v2.w * w2, v3.w * w3)));
        }
        for (; j < nc; j++) {
            const float4* hr = (const float4*)(g_h + ss[j] * Dd);
            float w = sw[j];
            float4 v = hr[t];
            m.x = fmaxf(m.x, v.x * w);
            m.y = fmaxf(m.y, v.y * w);
            m.z = fmaxf(m.z, v.z * w);
            m.w = fmaxf(m.w, v.w * w);
        }
        __syncthreads();
    }
    float4 hv = ((const float4*)(g_h + d * Dd))[t];
    float x0 = hv.x + ((m.x == -INFINITY) ? 0.f : m.x);
    float x1 = hv.y + ((m.y == -INFINITY) ? 0.f : m.y);
    float x2 = hv.z + ((m.z == -INFINITY) ? 0.f : m.z);
    float x3 = hv.w + ((m.w == -INFINITY) ? 0.f : m.w);
    float h0 = __half2float(__float2half_rn(x0));
    float h1 = __half2float(__float2half_rn(x1));
    float h2 = __half2float(__float2half_rn(x2));
    float h3 = __half2float(__float2half_rn(x3));
    uint32_t hiA = pack_h2(x0, x1), hiB = pack_h2(x2, x3);
    uint32_t loA = pack_h2(x0 - h0, x1 - h1), loB = pack_h2(x2 - h2, x3 - h3);
    size_t ab = (size_t)d * KTOT + 4 * t;
    *(uint32_t*)(g_A + ab) = hiA;          *(uint32_t*)(g_A + ab + 2) = hiB;
    *(uint32_t*)(g_A + ab + Dd) = loA;     *(uint32_t*)(g_A + ab + Dd + 2) = loB;
}

// =================== K4: split-K x4 fp16 GEMM, 64x64, ldmatrix ===================
#define ROWB 144                   // bytes per smem row (72 halves)
#define ATILE_B (64 * ROWB)        // 9216
#define STAGE_B (2 * ATILE_B)      // 18432
__global__ __launch_bounds__(128, 4) void k_gemm_mma() {
    extern __shared__ __align__(16) unsigned char smem[];
    int tid = threadIdx.x;
    int lane = tid & 31, warp = tid >> 5;
    int bm = blockIdx.y * 64, bn = blockIdx.x * 64;
    int kz = blockIdx.z;
    int wm = (warp & 1) * 32, wn = (warp >> 1) * 32;

    uint32_t sbase = smem_u32(smem);
    uint32_t sA[3], sB[3];
#pragma unroll
    for (int st = 0; st < 3; st++) {
        sA[st] = sbase + st * STAGE_B;
        sB[st] = sA[st] + ATILE_B;
    }

    uint32_t aoff = (uint32_t)(wm + ((lane & 8) ? 8 : 0) + (lane & 7)) * ROWB
                  + ((lane & 16) ? 16 : 0);
    int lb = lane & 15;
    uint32_t boff = (uint32_t)(wn + (lb & 7)) * ROWB + ((lb & 8) ? 16 : 0);

    float acc[2][4][4];
#pragma unroll
    for (int mf = 0; mf < 2; mf++)
#pragma unroll
        for (int nf = 0; nf < 4; nf++)
#pragma unroll
            for (int r = 0; r < 4; r++) acc[mf][nf][r] = 0.f;

#define LOAD_CHUNK(cidx, st)                                                        \
    do {                                                                            \
        int k0 = kz * (KZC * KC2) + (cidx) * KC2;                                   \
        _Pragma("unroll")                                                           \
        for (int it = 0; it < 4; it++) {                                            \
            int idx = it * 128 + tid;                                               \
            int row = idx >> 3, seg = idx & 7;                                      \
            uint32_t da = sA[st] + row * ROWB + seg * 16;                           \
            uint32_t db = sB[st] + row * ROWB + seg * 16;                           \
            const void* pa = g_A + (size_t)(bm + row) * KTOT + k0 + seg * 8;        \
            const void* pb = g_B + (size_t)(bn + row) * KTOT + k0 + seg * 8;        \
            asm volatile("cp.async.cg.shared.global [%0], [%1], 16;" :: "r"(da), "l"(pa)); \
            asm volatile("cp.async.cg.shared.global [%0], [%1], 16;" :: "r"(db), "l"(pb)); \
        }                                                                           \
        asm volatile("cp.async.commit_group;" ::: "memory");                        \
    } while (0)

    LOAD_CHUNK(0, 0);
    LOAD_CHUNK(1, 1);

    for (int c = 0; c < KZC; c++) {
        int st = c % 3;
        if (c + 2 < KZC) {
            LOAD_CHUNK(c + 2, (c + 2) % 3);
            asm volatile("cp.async.wait_group 2;" ::: "memory");
        } else if (c + 1 < KZC) {
            asm volatile("cp.async.wait_group 1;" ::: "memory");
        } else {
            asm volatile("cp.async.wait_group 0;" ::: "memory");
        }
        __syncthreads();

        uint32_t aB = sA[st] + aoff;
        uint32_t bB = sB[st] + boff;
#pragma unroll
        for (int ks = 0; ks < 4; ks++) {
            uint32_t a[2][4];
            LDSM4(a[0][0], a[0][1], a[0][2], a[0][3], aB + ks * 32);
            LDSM4(a[1][0], a[1][1], a[1][2], a[1][3], aB + 16 * ROWB + ks * 32);
            uint32_t b[4][2];
#pragma unroll
            for (int nf = 0; nf < 4; nf++)
                LDSM2(b[nf][0], b[nf][1], bB + nf * 8 * ROWB + ks * 32);
#pragma unroll
            for (int mf = 0; mf < 2; mf++)
#pragma unroll
                for (int nf = 0; nf < 4; nf++) {
                    asm volatile(
                        "mma.sync.aligned.m16n8k16.row.col.f32.f16.f16.f32 "
                        "{%0,%1,%2,%3}, {%4,%5,%6,%7}, {%8,%9}, {%0,%1,%2,%3};"
                        : "+f"(acc[mf][nf][0]), "+f"(acc[mf][nf][1]),
                          "+f"(acc[mf][nf][2]), "+f"(acc[mf][nf][3])
                        : "r"(a[mf][0]), "r"(a[mf][1]), "r"(a[mf][2]), "r"(a[mf][3]),
                          "r"(b[nf][0]), "r"(b[nf][1]));
                }
        }
        __syncthreads();
    }

    float* dst = g_part + (size_t)kz * Nn * Dd;
#pragma unroll
    for (int mf = 0; mf < 2; mf++) {
        int row = bm + wm + mf * 16 + (lane >> 2);
#pragma unroll
        for (int nf = 0; nf < 4; nf++) {
            int col = bn + wn + nf * 8 + (lane & 3) * 2;
            *(float2*)(dst + row * Dd + col)       = make_float2(acc[mf][nf][0], acc[mf][nf][1]);
            *(float2*)(dst + (row + 8) * Dd + col) = make_float2(acc[mf][nf][2], acc[mf][nf][3]);
        }
    }
}

// =================== K5: combine partials + bias + residual + proj ===================
__global__ void k_post(const float* __restrict__ bg, const float* __restrict__ Wd) {
    int row = blockIdx.x;
    int t = threadIdx.x;   // 320
    int c = 4 * t;
    float4 p0 = *(const float4*)(g_part + (size_t)row * Dd + c);
    float4 p1 = *(const float4*)(g_part + (size_t)Nn * Dd + (size_t)row * Dd + c);
    float4 p2 = *(const float4*)(g_part + 2 * (size_t)Nn * Dd + (size_t)row * Dd + c);
    float4 p3 = *(const float4*)(g_part + 3 * (size_t)Nn * Dd + (size_t)row * Dd + c);
    float4 hb = *(const float4*)(g_h + (size_t)row * Dd + c);
    float4 bv = *(const float4*)(bg + c);
    float4 v;
    v.x = (p0.x + p1.x) + (p2.x + p3.x) + bv.x + hb.x;
    v.y = (p0.y + p1.y) + (p2.y + p3.y) + bv.y + hb.y;
    v.z = (p0.z + p1.z) + (p2.z + p3.z) + bv.z + hb.z;
    v.w = (p0.w + p1.w) + (p2.w + p3.w) + bv.w + hb.w;
    *(float4*)(g_no + (size_t)row * Dd + c) = v;
    float4 wv = *(const float4*)(Wd + c);
    float s = v.x * wv.x + v.y * wv.y + v.z * wv.z + v.w * wv.w;
#pragma unroll
    for (int o = 16; o; o >>= 1) s += __shfl_down_sync(0xffffffff, s, o);
    __shared__ float red[10];
    int lane = t & 31, wid = t >> 5;
    if (lane == 0) red[wid] = s;
    __syncthreads();
    if (t == 0) {
        float tot = 0.f;
#pragma unroll
        for (int q = 0; q < 10; q++) tot += red[q];
        g_p[row] = tot;
    }
}

// =================== K6: fused dis_pred + mask_pred ===================
__global__ void k_dismask(float* __restrict__ out, const float* __restrict__ bd,
                          const int* __restrict__ midx, const float* __restrict__ Wm,
                          const float* __restrict__ bm) {
    int t = threadIdx.x;   // 128
    if (blockIdx.x < Nn) {
        int i = blockIdx.x;
        __shared__ float ps[Nn];
        ps[t] = g_p[t]; ps[t + 128] = g_p[t + 128];
        ps[t + 256] = g_p[t + 256]; ps[t + 384] = g_p[t + 384];
        __syncthreads();
        float pi = ps[i];
        float b = bd[0];
        int j = 4 * t;
        float4 o;
        o.x = 1.0f / (1.0f + expf(-(ps[j + 0] - pi + b)));
        o.y = 1.0f / (1.0f + expf(-(ps[j + 1] - pi + b)));
        o.z = 1.0f / (1.0f + expf(-(ps[j + 2] - pi + b)));
        o.w = 1.0f / (1.0f + expf(-(ps[j + 3] - pi + b)));
        *(float4*)(out + i * Nn + j) = o;
    } else {
        int b = blockIdx.x - Nn;
        int r = midx[b];
        float s0 = 0.f, s1 = 0.f;
        for (int k = t; k < Dd; k += 128) {
            float v = g_no[r * Dd + k];
            s0 += v * Wm[k * 2 + 0];
            s1 += v * Wm[k * 2 + 1];
        }
        __shared__ float red[2][4];
        int lane = t & 31, wid = t >> 5;
#pragma unroll
        for (int o = 16; o; o >>= 1) {
            s0 += __shfl_down_sync(0xffffffff, s0, o);
            s1 += __shfl_down_sync(0xffffffff, s1, o);
        }
        if (lane == 0) { red[0][wid] = s0; red[1][wid] = s1; }
        __syncthreads();
        if (t == 0) {
            s0 = red[0][0] + red[0][1] + red[0][2] + red[0][3];
            s1 = red[1][0] + red[1][1] + red[1][2] + red[1][3];
            out[Nn * Nn + b * 2 + 0] = tanhf(s0 + bm[0]);
            out[Nn * Nn + b * 2 + 1] = tanhf(s1 + bm[1]);
        }
    }
}

extern "C" void kernel_launch(void* const* d_in, const int* in_sizes, int n_in,
                              void* d_out, int out_size) {
    const float* lm  = (const float*)d_in[0];
    const float* nf  = (const float*)d_in[1];
    const float* ew  = (const float*)d_in[2];
    const int*   src = (const int*)d_in[3];
    const int*   dst = (const int*)d_in[4];
    const int*   mi  = (const int*)d_in[5];
    const float* Wg  = (const float*)d_in[6];
    const float* bg  = (const float*)d_in[7];
    const float* Wd  = (const float*)d_in[8];
    const float* bd  = (const float*)d_in[9];
    const float* Wm  = (const float*)d_in[10];
    const float* bm  = (const float*)d_in[11];
    float* out = (float*)d_out;

    cudaFuncSetAttribute(k_gemm_mma, cudaFuncAttributeMaxDynamicSharedMemorySize,
                         3 * STAGE_B);

    k_prep<<<BH_BLKS + 1600, 256>>>(lm, nf, Wg);
    k_csr<<<1, 1024>>>(dst);
    k_neigh<<<Nn, 320>>>(src, ew);
    k_gemm_mma<<<dim3(Dd / 64, Nn / 64, NSPLIT), 128, 3 * STAGE_B>>>();
    k_post<<<Nn, 320>>>(bg, Wd);
    k_dismask<<<Nn + Mm, 128>>>(out, bd, mi, Wm, bm);
}